// round 4
// baseline (speedup 1.0000x reference)
#include <cuda_runtime.h>
#include <math.h>

#define BB   2
#define SS   2048
#define DD   1024
#define HH   16
#define DHD  64
#define MM   (BB * SS)   // 4096

// Scratch for Q, K, V projections: [B, S, D] each (layout identical to x).
__device__ float4 g_Qv[(size_t)MM * DD / 4];
__device__ float4 g_Kv[(size_t)MM * DD / 4];
__device__ float4 g_Vv[(size_t)MM * DD / 4];

// ---------------------------------------------------------------------------
// Fused QKV GEMM:  C[m,n] = sum_k X[m,k] * W[n,k] + b[n]
// M=4096, N=1024, K=1024.  blockIdx.z selects (Wq,bq,g_Q) / (Wk,..) / (Wv,..)
// Tiles: BM=128, BN=64, BK=16.  256 threads, each computes 8x4.
// ---------------------------------------------------------------------------
#define GBM 128
#define GBN 64
#define GBK 16
#define GPA (GBM + 4)   // padded pitch for As (floats), 132
#define GPB (GBN + 4)   // 68

__global__ __launch_bounds__(256) void qkv_gemm(
    const float* __restrict__ X,
    const float* __restrict__ Wq, const float* __restrict__ bq,
    const float* __restrict__ Wk, const float* __restrict__ bk,
    const float* __restrict__ Wv, const float* __restrict__ bv)
{
    __shared__ float As[GBK * GPA];
    __shared__ float Bs[GBK * GPB];

    const float* W; const float* bias; float* C;
    if (blockIdx.z == 0)      { W = Wq; bias = bq; C = (float*)g_Qv; }
    else if (blockIdx.z == 1) { W = Wk; bias = bk; C = (float*)g_Kv; }
    else                      { W = Wv; bias = bv; C = (float*)g_Vv; }

    const int tid = threadIdx.x;
    const int m0 = blockIdx.y * GBM;
    const int n0 = blockIdx.x * GBN;
    const int ty = tid >> 4;      // 0..15 -> 8 rows each
    const int tx = tid & 15;      // 0..15 -> 4 cols each

    float acc[8][4];
#pragma unroll
    for (int i = 0; i < 8; i++)
#pragma unroll
        for (int j = 0; j < 4; j++) acc[i][j] = 0.0f;

    for (int k0 = 0; k0 < DD; k0 += GBK) {
        // A tile: 128 rows x 16 k = 512 float4, 2 per thread (transposed)
#pragma unroll
        for (int p = 0; p < 2; p++) {
            int i = tid + p * 256;
            int row = i >> 2, quad = i & 3;
            float4 v = *(const float4*)(X + (size_t)(m0 + row) * DD + k0 + quad * 4);
            As[(quad * 4 + 0) * GPA + row] = v.x;
            As[(quad * 4 + 1) * GPA + row] = v.y;
            As[(quad * 4 + 2) * GPA + row] = v.z;
            As[(quad * 4 + 3) * GPA + row] = v.w;
        }
        // B tile: 64 rows x 16 k = 256 float4, 1 per thread (transposed)
        {
            int row = tid >> 2, quad = tid & 3;
            float4 v = *(const float4*)(W + (size_t)(n0 + row) * DD + k0 + quad * 4);
            Bs[(quad * 4 + 0) * GPB + row] = v.x;
            Bs[(quad * 4 + 1) * GPB + row] = v.y;
            Bs[(quad * 4 + 2) * GPB + row] = v.z;
            Bs[(quad * 4 + 3) * GPB + row] = v.w;
        }
        __syncthreads();

#pragma unroll
        for (int kk = 0; kk < GBK; kk++) {
            float4 a0 = *(const float4*)&As[kk * GPA + ty * 8];
            float4 a1 = *(const float4*)&As[kk * GPA + ty * 8 + 4];
            float4 bv4 = *(const float4*)&Bs[kk * GPB + tx * 4];
            float a[8] = {a0.x, a0.y, a0.z, a0.w, a1.x, a1.y, a1.z, a1.w};
            float bb[4] = {bv4.x, bv4.y, bv4.z, bv4.w};
#pragma unroll
            for (int i = 0; i < 8; i++)
#pragma unroll
                for (int j = 0; j < 4; j++)
                    acc[i][j] = fmaf(a[i], bb[j], acc[i][j]);
        }
        __syncthreads();
    }

    float4 bvec = *(const float4*)(bias + n0 + tx * 4);
#pragma unroll
    for (int i = 0; i < 8; i++) {
        float4 o;
        o.x = acc[i][0] + bvec.x;
        o.y = acc[i][1] + bvec.y;
        o.z = acc[i][2] + bvec.z;
        o.w = acc[i][3] + bvec.w;
        *(float4*)(C + (size_t)(m0 + ty * 8 + i) * DD + n0 + tx * 4) = o;
    }
}

// ---------------------------------------------------------------------------
// Flash-style attention with ANTI-causal mask (keep k > q, else -1e9).
// 64x64 q/k tiles, dh = 64. k-tiles start at the diagonal tile.
// DYNAMIC shared memory (49408 B > 48KB static limit):
//   Qs: 64x64  pitch 64  @ float ofs 0      (16384 B)
//   KPs:64x65  pitch 65  @ float ofs 4096   (16640 B)  K tile, reused for P
//   Vs: 64x64  pitch 64  @ float ofs 8256   (16384 B)
// ---------------------------------------------------------------------------
#define QP 64
#define KP 65
#define VP 64
#define ATTN_SMEM_FLOATS (64 * QP + 64 * KP + 64 * VP)   // 12352
#define ATTN_SMEM_BYTES  (ATTN_SMEM_FLOATS * 4)          // 49408
#define NEGV (-1000000000.0f)

__global__ __launch_bounds__(256) void attn_kernel(float* __restrict__ out)
{
    extern __shared__ float smem[];
    float* Qs  = smem;                 // 64*64
    float* KPs = smem + 64 * QP;       // 64*65
    float* Vs  = smem + 64 * QP + 64 * KP;   // 64*64

    const int tid = threadIdx.x;
    const int qt = blockIdx.x;          // q tile 0..31
    const int bh = blockIdx.y;          // b*H + h
    const int b = bh >> 4, h = bh & 15;
    const int ty = tid >> 4;            // 0..15 -> 4 q rows
    const int tx = tid & 15;            // 0..15 -> 4 k (or d) cols

    const float* Qp = (const float*)g_Qv + (size_t)b * SS * DD + (size_t)h * DHD;
    const float* Kp = (const float*)g_Kv + (size_t)b * SS * DD + (size_t)h * DHD;
    const float* Vp = (const float*)g_Vv + (size_t)b * SS * DD + (size_t)h * DHD;

    // Load Q tile [64 q][64 d]
    for (int i = tid; i < 64 * 16; i += 256) {
        int row = i >> 4, q4 = i & 15;
        float4 v = *(const float4*)(Qp + (size_t)(qt * 64 + row) * DD + q4 * 4);
        *(float4*)&Qs[row * QP + q4 * 4] = v;
    }

    float mrow[4], lrow[4], acc[4][4];
#pragma unroll
    for (int i = 0; i < 4; i++) {
        mrow[i] = -INFINITY;
        lrow[i] = 0.0f;
#pragma unroll
        for (int j = 0; j < 4; j++) acc[i][j] = 0.0f;
    }

    const int q0 = qt * 64 + ty * 4;

    for (int kt = qt; kt < SS / 64; kt++) {
        __syncthreads();   // previous iteration's P/V reads complete
        for (int i = tid; i < 64 * 16; i += 256) {
            int row = i >> 4, q4 = i & 15;
            float4 kv = *(const float4*)(Kp + (size_t)(kt * 64 + row) * DD + q4 * 4);
            KPs[row * KP + q4 * 4 + 0] = kv.x;
            KPs[row * KP + q4 * 4 + 1] = kv.y;
            KPs[row * KP + q4 * 4 + 2] = kv.z;
            KPs[row * KP + q4 * 4 + 3] = kv.w;
            float4 vv = *(const float4*)(Vp + (size_t)(kt * 64 + row) * DD + q4 * 4);
            *(float4*)&Vs[row * VP + q4 * 4] = vv;
        }
        __syncthreads();

        // S tile: s[i][j] = dot(Q[q0+i,:], K[k0+j,:])
        float sv[4][4];
#pragma unroll
        for (int i = 0; i < 4; i++)
#pragma unroll
            for (int j = 0; j < 4; j++) sv[i][j] = 0.0f;

#pragma unroll 8
        for (int d = 0; d < DHD; d++) {
            float a0 = Qs[(ty * 4 + 0) * QP + d];
            float a1 = Qs[(ty * 4 + 1) * QP + d];
            float a2 = Qs[(ty * 4 + 2) * QP + d];
            float a3 = Qs[(ty * 4 + 3) * QP + d];
            float b0 = KPs[(tx * 4 + 0) * KP + d];
            float b1 = KPs[(tx * 4 + 1) * KP + d];
            float b2 = KPs[(tx * 4 + 2) * KP + d];
            float b3 = KPs[(tx * 4 + 3) * KP + d];
            sv[0][0] = fmaf(a0, b0, sv[0][0]); sv[0][1] = fmaf(a0, b1, sv[0][1]);
            sv[0][2] = fmaf(a0, b2, sv[0][2]); sv[0][3] = fmaf(a0, b3, sv[0][3]);
            sv[1][0] = fmaf(a1, b0, sv[1][0]); sv[1][1] = fmaf(a1, b1, sv[1][1]);
            sv[1][2] = fmaf(a1, b2, sv[1][2]); sv[1][3] = fmaf(a1, b3, sv[1][3]);
            sv[2][0] = fmaf(a2, b0, sv[2][0]); sv[2][1] = fmaf(a2, b1, sv[2][1]);
            sv[2][2] = fmaf(a2, b2, sv[2][2]); sv[2][3] = fmaf(a2, b3, sv[2][3]);
            sv[3][0] = fmaf(a3, b0, sv[3][0]); sv[3][1] = fmaf(a3, b1, sv[3][1]);
            sv[3][2] = fmaf(a3, b2, sv[3][2]); sv[3][3] = fmaf(a3, b3, sv[3][3]);
        }

        // Scale (1/sqrt(16) = 1/4), mask (keep k > q), online softmax update
        const int k0 = kt * 64 + tx * 4;
        float p[4][4];
#pragma unroll
        for (int i = 0; i < 4; i++) {
            float mx = -INFINITY;
#pragma unroll
            for (int j = 0; j < 4; j++) {
                float v = sv[i][j] * 0.25f;
                if (k0 + j <= q0 + i) v = NEGV;
                sv[i][j] = v;
                mx = fmaxf(mx, v);
            }
#pragma unroll
            for (int o = 8; o > 0; o >>= 1)
                mx = fmaxf(mx, __shfl_xor_sync(0xffffffffu, mx, o));
            float mn = fmaxf(mrow[i], mx);
            float fac = __expf(mrow[i] - mn);   // exp(-inf)=0 on first tile
            float rs = 0.0f;
#pragma unroll
            for (int j = 0; j < 4; j++) {
                p[i][j] = __expf(sv[i][j] - mn);
                rs += p[i][j];
            }
#pragma unroll
            for (int o = 8; o > 0; o >>= 1)
                rs += __shfl_xor_sync(0xffffffffu, rs, o);
            lrow[i] = lrow[i] * fac + rs;
            mrow[i] = mn;
#pragma unroll
            for (int j = 0; j < 4; j++) acc[i][j] *= fac;
        }

        __syncthreads();   // done reading K tile
        // Store P into KPs, natural [q][k], pitch 65
#pragma unroll
        for (int i = 0; i < 4; i++)
#pragma unroll
            for (int j = 0; j < 4; j++)
                KPs[(ty * 4 + i) * KP + tx * 4 + j] = p[i][j];
        __syncthreads();

        // O += P @ V   (acc cols are dh dims: tx*4+j)
#pragma unroll 4
        for (int kk = 0; kk < 64; kk++) {
            float p0 = KPs[(ty * 4 + 0) * KP + kk];
            float p1 = KPs[(ty * 4 + 1) * KP + kk];
            float p2 = KPs[(ty * 4 + 2) * KP + kk];
            float p3 = KPs[(ty * 4 + 3) * KP + kk];
            float v0 = Vs[kk * VP + tx * 4 + 0];
            float v1 = Vs[kk * VP + tx * 4 + 1];
            float v2 = Vs[kk * VP + tx * 4 + 2];
            float v3 = Vs[kk * VP + tx * 4 + 3];
            acc[0][0] = fmaf(p0, v0, acc[0][0]); acc[0][1] = fmaf(p0, v1, acc[0][1]);
            acc[0][2] = fmaf(p0, v2, acc[0][2]); acc[0][3] = fmaf(p0, v3, acc[0][3]);
            acc[1][0] = fmaf(p1, v0, acc[1][0]); acc[1][1] = fmaf(p1, v1, acc[1][1]);
            acc[1][2] = fmaf(p1, v2, acc[1][2]); acc[1][3] = fmaf(p1, v3, acc[1][3]);
            acc[2][0] = fmaf(p2, v0, acc[2][0]); acc[2][1] = fmaf(p2, v1, acc[2][1]);
            acc[2][2] = fmaf(p2, v2, acc[2][2]); acc[2][3] = fmaf(p2, v3, acc[2][3]);
            acc[3][0] = fmaf(p3, v0, acc[3][0]); acc[3][1] = fmaf(p3, v1, acc[3][1]);
            acc[3][2] = fmaf(p3, v2, acc[3][2]); acc[3][3] = fmaf(p3, v3, acc[3][3]);
        }
    }

    // Write out: out[b, q, h*64 + d]
#pragma unroll
    for (int i = 0; i < 4; i++) {
        float inv_l = 1.0f / lrow[i];
        float4 o;
        o.x = acc[i][0] * inv_l;
        o.y = acc[i][1] * inv_l;
        o.z = acc[i][2] * inv_l;
        o.w = acc[i][3] * inv_l;
        *(float4*)(out + ((size_t)b * SS + q0 + i) * DD + h * DHD + tx * 4) = o;
    }
}

// ---------------------------------------------------------------------------
// Fixup: row q = S-1 has ZERO unmasked keys -> reference softmax is uniform
// over ALL S keys -> out = mean_k V[b,k,h,:].
// ---------------------------------------------------------------------------
__global__ __launch_bounds__(256) void fix_last_row(float* __restrict__ out)
{
    __shared__ float red[256];
    const int bh = blockIdx.x;
    const int b = bh >> 4, h = bh & 15;
    const int d = threadIdx.x & 63;
    const int part = threadIdx.x >> 6;   // 0..3

    const float* vp = (const float*)g_Vv + (size_t)b * SS * DD + (size_t)h * DHD + d;
    float s = 0.0f;
    const int k_beg = part * (SS / 4), k_end = k_beg + SS / 4;
    for (int k = k_beg; k < k_end; k++)
        s += vp[(size_t)k * DD];
    red[threadIdx.x] = s;
    __syncthreads();
    if (part == 0) {
        float t = red[d] + red[64 + d] + red[128 + d] + red[192 + d];
        out[((size_t)b * SS + (SS - 1)) * DD + h * DHD + d] = t * (1.0f / SS);
    }
}

// ---------------------------------------------------------------------------
extern "C" void kernel_launch(void* const* d_in, const int* in_sizes, int n_in,
                              void* d_out, int out_size)
{
    const float* x  = (const float*)d_in[0];
    const float* Wq = (const float*)d_in[1];
    const float* bq = (const float*)d_in[2];
    const float* Wk = (const float*)d_in[3];
    const float* bk = (const float*)d_in[4];
    const float* Wv = (const float*)d_in[5];
    const float* bv = (const float*)d_in[6];
    float* out = (float*)d_out;

    static bool attr_done = false;
    if (!attr_done) {
        cudaFuncSetAttribute(attn_kernel,
                             cudaFuncAttributeMaxDynamicSharedMemorySize,
                             ATTN_SMEM_BYTES);
        attr_done = true;
    }

    dim3 g1(DD / GBN, MM / GBM, 3);           // (16, 32, 3)
    qkv_gemm<<<g1, 256>>>(x, Wq, bq, Wk, bk, Wv, bv);

    attn_kernel<<<dim3(SS / 64, BB * HH), 256, ATTN_SMEM_BYTES>>>(out);

    fix_last_row<<<BB * HH, 256>>>(out);
}

// round 6
// speedup vs baseline: 1.2896x; 1.2896x over previous
#include <cuda_runtime.h>
#include <cuda_bf16.h>
#include <math.h>

#define BB   2
#define SS   2048
#define DD   1024
#define HH   16
#define DHD  64
#define MM   (BB * SS)   // 4096

// Scratch for Q, K, V projections: [B, S, D] each (layout identical to x).
__device__ float4 g_Qv[(size_t)MM * DD / 4];
__device__ float4 g_Kv[(size_t)MM * DD / 4];
__device__ float4 g_Vv[(size_t)MM * DD / 4];

// bf16 hi/lo split operands
__device__ __nv_bfloat16 g_Xhi[(size_t)MM * DD];
__device__ __nv_bfloat16 g_Xlo[(size_t)MM * DD];
__device__ __nv_bfloat16 g_Whi[(size_t)3 * DD * DD];
__device__ __nv_bfloat16 g_Wlo[(size_t)3 * DD * DD];

// ---------------------------------------------------------------------------
// Split f32 -> bf16 hi + bf16 lo   (x ~= hi + lo, residual ~2^-16 * |x|)
// Destination resolved IN DEVICE CODE (device-global addresses must not be
// taken from host code -- on GB300/ATS that silently writes host memory).
// buf: 0 -> (g_Xhi, g_Xlo)      off = 0
//      1 -> (g_Whi+off, g_Wlo+off)
// ---------------------------------------------------------------------------
__global__ __launch_bounds__(256) void split_f32(
    const float* __restrict__ src, int buf, size_t off)
{
    __nv_bfloat16* hi = (buf == 0) ? g_Xhi : (g_Whi + off);
    __nv_bfloat16* lo = (buf == 0) ? g_Xlo : (g_Wlo + off);

    int i = (blockIdx.x * 256 + threadIdx.x) * 4;
    float4 v = *(const float4*)(src + i);
    __nv_bfloat16 h0 = __float2bfloat16(v.x);
    __nv_bfloat16 h1 = __float2bfloat16(v.y);
    __nv_bfloat16 h2 = __float2bfloat16(v.z);
    __nv_bfloat16 h3 = __float2bfloat16(v.w);
    __nv_bfloat16 l0 = __float2bfloat16(v.x - __bfloat162float(h0));
    __nv_bfloat16 l1 = __float2bfloat16(v.y - __bfloat162float(h1));
    __nv_bfloat16 l2 = __float2bfloat16(v.z - __bfloat162float(h2));
    __nv_bfloat16 l3 = __float2bfloat16(v.w - __bfloat162float(h3));
    __nv_bfloat162 hA; hA.x = h0; hA.y = h1;
    __nv_bfloat162 hB; hB.x = h2; hB.y = h3;
    __nv_bfloat162 lA; lA.x = l0; lA.y = l1;
    __nv_bfloat162 lB; lB.x = l2; lB.y = l3;
    *(__nv_bfloat162*)(hi + i)     = hA;
    *(__nv_bfloat162*)(hi + i + 2) = hB;
    *(__nv_bfloat162*)(lo + i)     = lA;
    *(__nv_bfloat162*)(lo + i + 2) = lB;
}

// ---------------------------------------------------------------------------
// Tensor-core QKV GEMM via mma.sync m16n8k16 bf16, split-precision (3 MMAs).
// C[m,n] = sum_k X[m,k] * W[n,k] + b[n].   Block tile 128x128, BK=32 bf16.
// 8 warps: 4 along M x 2 along N, warp tile 32x64.
// smem pitch = 20 words (40 bf16): fragment loads are bank-conflict-free.
// ---------------------------------------------------------------------------
#define TBM 128
#define TBN 128
#define TBK 32
#define SPW 20   // smem pitch in 32-bit words (= 40 bf16 per row)

__device__ __forceinline__ void mma_bf16(float (&c)[4], const unsigned (&a)[4],
                                         const unsigned (&b)[2])
{
    asm volatile(
        "mma.sync.aligned.m16n8k16.row.col.f32.bf16.bf16.f32 "
        "{%0,%1,%2,%3}, {%4,%5,%6,%7}, {%8,%9}, {%0,%1,%2,%3};"
        : "+f"(c[0]), "+f"(c[1]), "+f"(c[2]), "+f"(c[3])
        : "r"(a[0]), "r"(a[1]), "r"(a[2]), "r"(a[3]), "r"(b[0]), "r"(b[1]));
}

__global__ __launch_bounds__(256) void qkv_gemm_tc(
    const float* __restrict__ bq,
    const float* __restrict__ bk,
    const float* __restrict__ bv)
{
    __shared__ unsigned sAhi[TBM * SPW];   // 10240 B each
    __shared__ unsigned sAlo[TBM * SPW];
    __shared__ unsigned sBhi[TBN * SPW];
    __shared__ unsigned sBlo[TBN * SPW];

    const int z = blockIdx.z;
    const float* bias = (z == 0) ? bq : (z == 1) ? bk : bv;
    float* C = (z == 0) ? (float*)g_Qv : (z == 1) ? (float*)g_Kv : (float*)g_Vv;
    const __nv_bfloat16* Whi = g_Whi + (size_t)z * DD * DD;
    const __nv_bfloat16* Wlo = g_Wlo + (size_t)z * DD * DD;

    const int tid = threadIdx.x;
    const int m0 = blockIdx.y * TBM;
    const int n0 = blockIdx.x * TBN;
    const int lane = tid & 31, wid = tid >> 5;
    const int wm = wid & 3;        // 0..3 -> 32 rows each
    const int wn = wid >> 2;       // 0..1 -> 64 cols each
    const int g = lane >> 2, th = lane & 3;

    float acc[2][8][4];
#pragma unroll
    for (int ms = 0; ms < 2; ms++)
#pragma unroll
        for (int ns = 0; ns < 8; ns++)
#pragma unroll
            for (int q = 0; q < 4; q++) acc[ms][ns][q] = 0.0f;

    for (int k0 = 0; k0 < DD; k0 += TBK) {
        __syncthreads();
        // Each tile: 128 rows x 32 bf16 = 512 uint4; 2 per thread per tile.
#pragma unroll
        for (int p = 0; p < 2; p++) {
            int idx = tid + p * 256;
            int row = idx >> 2, kc = idx & 3;   // kc*8 bf16 = kc*16 B
            size_t goffA = (size_t)(m0 + row) * DD + k0 + kc * 8;
            size_t goffB = (size_t)(n0 + row) * DD + k0 + kc * 8;
            ((uint4*)sAhi)[row * (SPW / 4) + kc] = *(const uint4*)(g_Xhi + goffA);
            ((uint4*)sAlo)[row * (SPW / 4) + kc] = *(const uint4*)(g_Xlo + goffA);
            ((uint4*)sBhi)[row * (SPW / 4) + kc] = *(const uint4*)(Whi + goffB);
            ((uint4*)sBlo)[row * (SPW / 4) + kc] = *(const uint4*)(Wlo + goffB);
        }
        __syncthreads();

#pragma unroll
        for (int ks = 0; ks < 2; ks++) {       // two k16 steps in BK=32
            const int c = ks * 8 + th;
            unsigned ah[2][4], al[2][4];
#pragma unroll
            for (int ms = 0; ms < 2; ms++) {
                int r0 = wm * 32 + ms * 16 + g;
                ah[ms][0] = sAhi[r0 * SPW + c];
                ah[ms][1] = sAhi[(r0 + 8) * SPW + c];
                ah[ms][2] = sAhi[r0 * SPW + c + 4];
                ah[ms][3] = sAhi[(r0 + 8) * SPW + c + 4];
                al[ms][0] = sAlo[r0 * SPW + c];
                al[ms][1] = sAlo[(r0 + 8) * SPW + c];
                al[ms][2] = sAlo[r0 * SPW + c + 4];
                al[ms][3] = sAlo[(r0 + 8) * SPW + c + 4];
            }
#pragma unroll
            for (int ns = 0; ns < 8; ns++) {
                int n = wn * 64 + ns * 8 + g;
                unsigned bh[2] = { sBhi[n * SPW + c], sBhi[n * SPW + c + 4] };
                unsigned bl[2] = { sBlo[n * SPW + c], sBlo[n * SPW + c + 4] };
#pragma unroll
                for (int ms = 0; ms < 2; ms++) {
                    mma_bf16(acc[ms][ns], ah[ms], bh);   // hi*hi
                    mma_bf16(acc[ms][ns], ah[ms], bl);   // hi*lo
                    mma_bf16(acc[ms][ns], al[ms], bh);   // lo*hi
                }
            }
        }
    }

    // Epilogue: c0,c1 -> (row, n..n+1), c2,c3 -> (row+8, n..n+1)
#pragma unroll
    for (int ms = 0; ms < 2; ms++) {
        int m = m0 + wm * 32 + ms * 16 + g;
#pragma unroll
        for (int ns = 0; ns < 8; ns++) {
            int n = n0 + wn * 64 + ns * 8 + th * 2;
            float2 bb = *(const float2*)&bias[n];
            float2 o0, o1;
            o0.x = acc[ms][ns][0] + bb.x;  o0.y = acc[ms][ns][1] + bb.y;
            o1.x = acc[ms][ns][2] + bb.x;  o1.y = acc[ms][ns][3] + bb.y;
            *(float2*)&C[(size_t)m * DD + n] = o0;
            *(float2*)&C[(size_t)(m + 8) * DD + n] = o1;
        }
    }
}

// ---------------------------------------------------------------------------
// Flash-style attention with ANTI-causal mask (keep k > q, else -1e9).
// Unchanged (passing since R4).
// ---------------------------------------------------------------------------
#define QP 64
#define KP 65
#define VP 64
#define ATTN_SMEM_FLOATS (64 * QP + 64 * KP + 64 * VP)
#define ATTN_SMEM_BYTES  (ATTN_SMEM_FLOATS * 4)
#define NEGV (-1000000000.0f)

__global__ __launch_bounds__(256) void attn_kernel(float* __restrict__ out)
{
    extern __shared__ float smem[];
    float* Qs  = smem;
    float* KPs = smem + 64 * QP;
    float* Vs  = smem + 64 * QP + 64 * KP;

    const int tid = threadIdx.x;
    const int qt = blockIdx.x;
    const int bh = blockIdx.y;
    const int b = bh >> 4, h = bh & 15;
    const int ty = tid >> 4;
    const int tx = tid & 15;

    const float* Qp = (const float*)g_Qv + (size_t)b * SS * DD + (size_t)h * DHD;
    const float* Kp = (const float*)g_Kv + (size_t)b * SS * DD + (size_t)h * DHD;
    const float* Vp = (const float*)g_Vv + (size_t)b * SS * DD + (size_t)h * DHD;

    for (int i = tid; i < 64 * 16; i += 256) {
        int row = i >> 4, q4 = i & 15;
        float4 v = *(const float4*)(Qp + (size_t)(qt * 64 + row) * DD + q4 * 4);
        *(float4*)&Qs[row * QP + q4 * 4] = v;
    }

    float mrow[4], lrow[4], acc[4][4];
#pragma unroll
    for (int i = 0; i < 4; i++) {
        mrow[i] = -INFINITY;
        lrow[i] = 0.0f;
#pragma unroll
        for (int j = 0; j < 4; j++) acc[i][j] = 0.0f;
    }

    const int q0 = qt * 64 + ty * 4;

    for (int kt = qt; kt < SS / 64; kt++) {
        __syncthreads();
        for (int i = tid; i < 64 * 16; i += 256) {
            int row = i >> 4, q4 = i & 15;
            float4 kv = *(const float4*)(Kp + (size_t)(kt * 64 + row) * DD + q4 * 4);
            KPs[row * KP + q4 * 4 + 0] = kv.x;
            KPs[row * KP + q4 * 4 + 1] = kv.y;
            KPs[row * KP + q4 * 4 + 2] = kv.z;
            KPs[row * KP + q4 * 4 + 3] = kv.w;
            float4 vv = *(const float4*)(Vp + (size_t)(kt * 64 + row) * DD + q4 * 4);
            *(float4*)&Vs[row * VP + q4 * 4] = vv;
        }
        __syncthreads();

        float sv[4][4];
#pragma unroll
        for (int i = 0; i < 4; i++)
#pragma unroll
            for (int j = 0; j < 4; j++) sv[i][j] = 0.0f;

#pragma unroll 8
        for (int d = 0; d < DHD; d++) {
            float a0 = Qs[(ty * 4 + 0) * QP + d];
            float a1 = Qs[(ty * 4 + 1) * QP + d];
            float a2 = Qs[(ty * 4 + 2) * QP + d];
            float a3 = Qs[(ty * 4 + 3) * QP + d];
            float b0 = KPs[(tx * 4 + 0) * KP + d];
            float b1 = KPs[(tx * 4 + 1) * KP + d];
            float b2 = KPs[(tx * 4 + 2) * KP + d];
            float b3 = KPs[(tx * 4 + 3) * KP + d];
            sv[0][0] = fmaf(a0, b0, sv[0][0]); sv[0][1] = fmaf(a0, b1, sv[0][1]);
            sv[0][2] = fmaf(a0, b2, sv[0][2]); sv[0][3] = fmaf(a0, b3, sv[0][3]);
            sv[1][0] = fmaf(a1, b0, sv[1][0]); sv[1][1] = fmaf(a1, b1, sv[1][1]);
            sv[1][2] = fmaf(a1, b2, sv[1][2]); sv[1][3] = fmaf(a1, b3, sv[1][3]);
            sv[2][0] = fmaf(a2, b0, sv[2][0]); sv[2][1] = fmaf(a2, b1, sv[2][1]);
            sv[2][2] = fmaf(a2, b2, sv[2][2]); sv[2][3] = fmaf(a2, b3, sv[2][3]);
            sv[3][0] = fmaf(a3, b0, sv[3][0]); sv[3][1] = fmaf(a3, b1, sv[3][1]);
            sv[3][2] = fmaf(a3, b2, sv[3][2]); sv[3][3] = fmaf(a3, b3, sv[3][3]);
        }

        const int k0 = kt * 64 + tx * 4;
        float p[4][4];
#pragma unroll
        for (int i = 0; i < 4; i++) {
            float mx = -INFINITY;
#pragma unroll
            for (int j = 0; j < 4; j++) {
                float v = sv[i][j] * 0.25f;
                if (k0 + j <= q0 + i) v = NEGV;
                sv[i][j] = v;
                mx = fmaxf(mx, v);
            }
#pragma unroll
            for (int o = 8; o > 0; o >>= 1)
                mx = fmaxf(mx, __shfl_xor_sync(0xffffffffu, mx, o));
            float mn = fmaxf(mrow[i], mx);
            float fac = __expf(mrow[i] - mn);
            float rs = 0.0f;
#pragma unroll
            for (int j = 0; j < 4; j++) {
                p[i][j] = __expf(sv[i][j] - mn);
                rs += p[i][j];
            }
#pragma unroll
            for (int o = 8; o > 0; o >>= 1)
                rs += __shfl_xor_sync(0xffffffffu, rs, o);
            lrow[i] = lrow[i] * fac + rs;
            mrow[i] = mn;
#pragma unroll
            for (int j = 0; j < 4; j++) acc[i][j] *= fac;
        }

        __syncthreads();
#pragma unroll
        for (int i = 0; i < 4; i++)
#pragma unroll
            for (int j = 0; j < 4; j++)
                KPs[(ty * 4 + i) * KP + tx * 4 + j] = p[i][j];
        __syncthreads();

#pragma unroll 4
        for (int kk = 0; kk < 64; kk++) {
            float p0 = KPs[(ty * 4 + 0) * KP + kk];
            float p1 = KPs[(ty * 4 + 1) * KP + kk];
            float p2 = KPs[(ty * 4 + 2) * KP + kk];
            float p3 = KPs[(ty * 4 + 3) * KP + kk];
            float v0 = Vs[kk * VP + tx * 4 + 0];
            float v1 = Vs[kk * VP + tx * 4 + 1];
            float v2 = Vs[kk * VP + tx * 4 + 2];
            float v3 = Vs[kk * VP + tx * 4 + 3];
            acc[0][0] = fmaf(p0, v0, acc[0][0]); acc[0][1] = fmaf(p0, v1, acc[0][1]);
            acc[0][2] = fmaf(p0, v2, acc[0][2]); acc[0][3] = fmaf(p0, v3, acc[0][3]);
            acc[1][0] = fmaf(p1, v0, acc[1][0]); acc[1][1] = fmaf(p1, v1, acc[1][1]);
            acc[1][2] = fmaf(p1, v2, acc[1][2]); acc[1][3] = fmaf(p1, v3, acc[1][3]);
            acc[2][0] = fmaf(p2, v0, acc[2][0]); acc[2][1] = fmaf(p2, v1, acc[2][1]);
            acc[2][2] = fmaf(p2, v2, acc[2][2]); acc[2][3] = fmaf(p2, v3, acc[2][3]);
            acc[3][0] = fmaf(p3, v0, acc[3][0]); acc[3][1] = fmaf(p3, v1, acc[3][1]);
            acc[3][2] = fmaf(p3, v2, acc[3][2]); acc[3][3] = fmaf(p3, v3, acc[3][3]);
        }
    }

#pragma unroll
    for (int i = 0; i < 4; i++) {
        float inv_l = 1.0f / lrow[i];
        float4 o;
        o.x = acc[i][0] * inv_l;
        o.y = acc[i][1] * inv_l;
        o.z = acc[i][2] * inv_l;
        o.w = acc[i][3] * inv_l;
        *(float4*)(out + ((size_t)b * SS + q0 + i) * DD + h * DHD + tx * 4) = o;
    }
}

// ---------------------------------------------------------------------------
// Fixup: row q = S-1 -> uniform softmax over ALL S keys -> mean_k V.
// ---------------------------------------------------------------------------
__global__ __launch_bounds__(256) void fix_last_row(float* __restrict__ out)
{
    __shared__ float red[256];
    const int bh = blockIdx.x;
    const int b = bh >> 4, h = bh & 15;
    const int d = threadIdx.x & 63;
    const int part = threadIdx.x >> 6;

    const float* vp = (const float*)g_Vv + (size_t)b * SS * DD + (size_t)h * DHD + d;
    float s = 0.0f;
    const int k_beg = part * (SS / 4), k_end = k_beg + SS / 4;
    for (int k = k_beg; k < k_end; k++)
        s += vp[(size_t)k * DD];
    red[threadIdx.x] = s;
    __syncthreads();
    if (part == 0) {
        float t = red[d] + red[64 + d] + red[128 + d] + red[192 + d];
        out[((size_t)b * SS + (SS - 1)) * DD + h * DHD + d] = t * (1.0f / SS);
    }
}

// ---------------------------------------------------------------------------
extern "C" void kernel_launch(void* const* d_in, const int* in_sizes, int n_in,
                              void* d_out, int out_size)
{
    const float* x  = (const float*)d_in[0];
    const float* Wq = (const float*)d_in[1];
    const float* bq = (const float*)d_in[2];
    const float* Wk = (const float*)d_in[3];
    const float* bk = (const float*)d_in[4];
    const float* Wv = (const float*)d_in[5];
    const float* bv = (const float*)d_in[6];
    float* out = (float*)d_out;

    static bool attr_done = false;
    if (!attr_done) {
        cudaFuncSetAttribute(attn_kernel,
                             cudaFuncAttributeMaxDynamicSharedMemorySize,
                             ATTN_SMEM_BYTES);
        attr_done = true;
    }

    // Split inputs into bf16 hi/lo (destinations resolved device-side)
    split_f32<<<MM * DD / 1024, 256>>>(x, 0, 0);
    split_f32<<<DD * DD / 1024, 256>>>(Wq, 1, 0);
    split_f32<<<DD * DD / 1024, 256>>>(Wk, 1, (size_t)DD * DD);
    split_f32<<<DD * DD / 1024, 256>>>(Wv, 1, (size_t)2 * DD * DD);

    // Tensor-core QKV projections
    dim3 gt(DD / TBN, MM / TBM, 3);   // (8, 32, 3)
    qkv_gemm_tc<<<gt, 256>>>(bq, bk, bv);

    attn_kernel<<<dim3(SS / 64, BB * HH), 256, ATTN_SMEM_BYTES>>>(out);

    fix_last_row<<<BB * HH, 256>>>(out);
}

// round 7
// speedup vs baseline: 2.4164x; 1.8737x over previous
#include <cuda_runtime.h>
#include <cuda_bf16.h>
#include <cuda_fp16.h>
#include <math.h>

#define BB   2
#define SS   2048
#define DD   1024
#define HH   16
#define DHD  64
#define MM   (BB * SS)   // 4096

// Scratch for Q, K, V projections: [B, S, D] each (layout identical to x).
__device__ float4 g_Qv[(size_t)MM * DD / 4];
__device__ float4 g_Kv[(size_t)MM * DD / 4];
__device__ float4 g_Vv[(size_t)MM * DD / 4];

// bf16 hi/lo split operands for the projection GEMMs
__device__ __nv_bfloat16 g_Xhi[(size_t)MM * DD];
__device__ __nv_bfloat16 g_Xlo[(size_t)MM * DD];
__device__ __nv_bfloat16 g_Whi[(size_t)3 * DD * DD];
__device__ __nv_bfloat16 g_Wlo[(size_t)3 * DD * DD];

// ---------------------------------------------------------------------------
// packing helpers
// ---------------------------------------------------------------------------
__device__ __forceinline__ unsigned pkb2(__nv_bfloat16 a, __nv_bfloat16 b) {
    __nv_bfloat162 t; t.x = a; t.y = b; return *(unsigned*)&t;
}
__device__ __forceinline__ unsigned pkbf(float a, float b) {
    __nv_bfloat162 t = __floats2bfloat162_rn(a, b); return *(unsigned*)&t;
}
__device__ __forceinline__ unsigned pkh(float a, float b) {
    __half2 t = __floats2half2_rn(a, b); return *(unsigned*)&t;
}

// ---------------------------------------------------------------------------
// Split f32 -> bf16 hi + bf16 lo.  Destinations resolved IN DEVICE CODE.
// ---------------------------------------------------------------------------
__global__ __launch_bounds__(256) void split_f32(
    const float* __restrict__ src, int buf, size_t off)
{
    __nv_bfloat16* hi = (buf == 0) ? g_Xhi : (g_Whi + off);
    __nv_bfloat16* lo = (buf == 0) ? g_Xlo : (g_Wlo + off);

    int i = (blockIdx.x * 256 + threadIdx.x) * 4;
    float4 v = *(const float4*)(src + i);
    __nv_bfloat16 h0 = __float2bfloat16(v.x);
    __nv_bfloat16 h1 = __float2bfloat16(v.y);
    __nv_bfloat16 h2 = __float2bfloat16(v.z);
    __nv_bfloat16 h3 = __float2bfloat16(v.w);
    *(unsigned*)(hi + i)     = pkb2(h0, h1);
    *(unsigned*)(hi + i + 2) = pkb2(h2, h3);
    *(unsigned*)(lo + i)     = pkbf(v.x - __bfloat162float(h0),
                                    v.y - __bfloat162float(h1));
    *(unsigned*)(lo + i + 2) = pkbf(v.z - __bfloat162float(h2),
                                    v.w - __bfloat162float(h3));
}

// ---------------------------------------------------------------------------
// mma wrappers
// ---------------------------------------------------------------------------
__device__ __forceinline__ void mma_bf16(float (&c)[4], const unsigned (&a)[4],
                                         const unsigned (&b)[2])
{
    asm volatile(
        "mma.sync.aligned.m16n8k16.row.col.f32.bf16.bf16.f32 "
        "{%0,%1,%2,%3}, {%4,%5,%6,%7}, {%8,%9}, {%0,%1,%2,%3};"
        : "+f"(c[0]), "+f"(c[1]), "+f"(c[2]), "+f"(c[3])
        : "r"(a[0]), "r"(a[1]), "r"(a[2]), "r"(a[3]), "r"(b[0]), "r"(b[1]));
}
__device__ __forceinline__ void mma_f16(float (&c)[4], const unsigned (&a)[4],
                                        const unsigned (&b)[2])
{
    asm volatile(
        "mma.sync.aligned.m16n8k16.row.col.f32.f16.f16.f32 "
        "{%0,%1,%2,%3}, {%4,%5,%6,%7}, {%8,%9}, {%0,%1,%2,%3};"
        : "+f"(c[0]), "+f"(c[1]), "+f"(c[2]), "+f"(c[3])
        : "r"(a[0]), "r"(a[1]), "r"(a[2]), "r"(a[3]), "r"(b[0]), "r"(b[1]));
}

// ---------------------------------------------------------------------------
// Tensor-core QKV GEMM (unchanged, passing).
// ---------------------------------------------------------------------------
#define TBM 128
#define TBN 128
#define TBK 32
#define SPW 20

__global__ __launch_bounds__(256) void qkv_gemm_tc(
    const float* __restrict__ bq,
    const float* __restrict__ bk,
    const float* __restrict__ bv)
{
    __shared__ unsigned sAhi[TBM * SPW];
    __shared__ unsigned sAlo[TBM * SPW];
    __shared__ unsigned sBhi[TBN * SPW];
    __shared__ unsigned sBlo[TBN * SPW];

    const int z = blockIdx.z;
    const float* bias = (z == 0) ? bq : (z == 1) ? bk : bv;
    float* C = (z == 0) ? (float*)g_Qv : (z == 1) ? (float*)g_Kv : (float*)g_Vv;
    const __nv_bfloat16* Whi = g_Whi + (size_t)z * DD * DD;
    const __nv_bfloat16* Wlo = g_Wlo + (size_t)z * DD * DD;

    const int tid = threadIdx.x;
    const int m0 = blockIdx.y * TBM;
    const int n0 = blockIdx.x * TBN;
    const int lane = tid & 31, wid = tid >> 5;
    const int wm = wid & 3;
    const int wn = wid >> 2;
    const int g = lane >> 2, th = lane & 3;

    float acc[2][8][4];
#pragma unroll
    for (int ms = 0; ms < 2; ms++)
#pragma unroll
        for (int ns = 0; ns < 8; ns++)
#pragma unroll
            for (int q = 0; q < 4; q++) acc[ms][ns][q] = 0.0f;

    for (int k0 = 0; k0 < DD; k0 += TBK) {
        __syncthreads();
#pragma unroll
        for (int p = 0; p < 2; p++) {
            int idx = tid + p * 256;
            int row = idx >> 2, kc = idx & 3;
            size_t goffA = (size_t)(m0 + row) * DD + k0 + kc * 8;
            size_t goffB = (size_t)(n0 + row) * DD + k0 + kc * 8;
            ((uint4*)sAhi)[row * (SPW / 4) + kc] = *(const uint4*)(g_Xhi + goffA);
            ((uint4*)sAlo)[row * (SPW / 4) + kc] = *(const uint4*)(g_Xlo + goffA);
            ((uint4*)sBhi)[row * (SPW / 4) + kc] = *(const uint4*)(Whi + goffB);
            ((uint4*)sBlo)[row * (SPW / 4) + kc] = *(const uint4*)(Wlo + goffB);
        }
        __syncthreads();

#pragma unroll
        for (int ks = 0; ks < 2; ks++) {
            const int c = ks * 8 + th;
            unsigned ah[2][4], al[2][4];
#pragma unroll
            for (int ms = 0; ms < 2; ms++) {
                int r0 = wm * 32 + ms * 16 + g;
                ah[ms][0] = sAhi[r0 * SPW + c];
                ah[ms][1] = sAhi[(r0 + 8) * SPW + c];
                ah[ms][2] = sAhi[r0 * SPW + c + 4];
                ah[ms][3] = sAhi[(r0 + 8) * SPW + c + 4];
                al[ms][0] = sAlo[r0 * SPW + c];
                al[ms][1] = sAlo[(r0 + 8) * SPW + c];
                al[ms][2] = sAlo[r0 * SPW + c + 4];
                al[ms][3] = sAlo[(r0 + 8) * SPW + c + 4];
            }
#pragma unroll
            for (int ns = 0; ns < 8; ns++) {
                int n = wn * 64 + ns * 8 + g;
                unsigned bh2[2] = { sBhi[n * SPW + c], sBhi[n * SPW + c + 4] };
                unsigned bl2[2] = { sBlo[n * SPW + c], sBlo[n * SPW + c + 4] };
#pragma unroll
                for (int ms = 0; ms < 2; ms++) {
                    mma_bf16(acc[ms][ns], ah[ms], bh2);
                    mma_bf16(acc[ms][ns], ah[ms], bl2);
                    mma_bf16(acc[ms][ns], al[ms], bh2);
                }
            }
        }
    }

#pragma unroll
    for (int ms = 0; ms < 2; ms++) {
        int m = m0 + wm * 32 + ms * 16 + g;
#pragma unroll
        for (int ns = 0; ns < 8; ns++) {
            int n = n0 + wn * 64 + ns * 8 + th * 2;
            float2 bb = *(const float2*)&bias[n];
            float2 o0, o1;
            o0.x = acc[ms][ns][0] + bb.x;  o0.y = acc[ms][ns][1] + bb.y;
            o1.x = acc[ms][ns][2] + bb.x;  o1.y = acc[ms][ns][3] + bb.y;
            *(float2*)&C[(size_t)m * DD + n] = o0;
            *(float2*)&C[(size_t)(m + 8) * DD + n] = o1;
        }
    }
}

// ---------------------------------------------------------------------------
// Tensor-core flash attention, ANTI-causal mask (keep k > q).
// Block: 128 q rows (8 warps x m16), k tiles of 64, dh=64.
// S = QK^T in split-bf16 (3 MMAs); P.V in fp16 (1 MMA).
// smem word pitch 36 -> all fragment LDS bank-conflict-free.
// V B-fragments via ldmatrix.x2.trans (no transpose stores).
// ---------------------------------------------------------------------------
#define PW 36                         // word pitch (= 72 halfwords)
#define OQH 0
#define OQL (128 * PW)                // 4608
#define OKH (2 * 128 * PW)            // 9216
#define OKL (OKH + 64 * PW)           // 11520
#define OVH (OKL + 64 * PW)           // 13824
#define ATTN2_WORDS (OVH + 64 * PW)   // 16128
#define ATTN2_BYTES (ATTN2_WORDS * 4) // 64512
#define NEGV (-1000000000.0f)

__global__ __launch_bounds__(256) void attn_tc(float* __restrict__ out)
{
    extern __shared__ unsigned sm[];
    const int tid = threadIdx.x;
    const int qt = blockIdx.x;          // 0..15 (128-row q tiles)
    const int bh = blockIdx.y;
    const int b = bh >> 4, h = bh & 15;
    const int lane = tid & 31, wm = tid >> 5;   // 8 warps, m16 each
    const int g = lane >> 2, th = lane & 3;

    const float* Qp = (const float*)g_Qv + (size_t)b * SS * DD + (size_t)h * DHD;
    const float* Kp = (const float*)g_Kv + (size_t)b * SS * DD + (size_t)h * DHD;
    const float* Vp = (const float*)g_Vv + (size_t)b * SS * DD + (size_t)h * DHD;

    const int q0 = qt * 128;

    // Load + split Q tile (128 x 64) into bf16 hi/lo smem
    for (int i = tid; i < 2048; i += 256) {
        int row = i >> 4, d4 = i & 15;
        float4 v = *(const float4*)(Qp + (size_t)(q0 + row) * DD + d4 * 4);
        __nv_bfloat16 h0 = __float2bfloat16(v.x);
        __nv_bfloat16 h1 = __float2bfloat16(v.y);
        __nv_bfloat16 h2 = __float2bfloat16(v.z);
        __nv_bfloat16 h3 = __float2bfloat16(v.w);
        sm[OQH + row * PW + d4 * 2]     = pkb2(h0, h1);
        sm[OQH + row * PW + d4 * 2 + 1] = pkb2(h2, h3);
        sm[OQL + row * PW + d4 * 2]     = pkbf(v.x - __bfloat162float(h0),
                                               v.y - __bfloat162float(h1));
        sm[OQL + row * PW + d4 * 2 + 1] = pkbf(v.z - __bfloat162float(h2),
                                               v.w - __bfloat162float(h3));
    }

    float m2[2] = { -INFINITY, -INFINITY };
    float l2[2] = { 0.0f, 0.0f };
    float oacc[8][4];
#pragma unroll
    for (int t = 0; t < 8; t++)
#pragma unroll
        for (int q = 0; q < 4; q++) oacc[t][q] = 0.0f;

    const unsigned smem_u32 = (unsigned)__cvta_generic_to_shared(sm);
    const int r0 = wm * 16 + g;              // A-fragment row within q tile
    const int qrow0 = q0 + r0, qrow1 = qrow0 + 8;

    for (int kt = qt * 2; kt < SS / 64; kt++) {
        __syncthreads();
        // Load K (split bf16) + V (fp16) tiles, 64 x 64 each
        for (int i = tid; i < 1024; i += 256) {
            int row = i >> 4, d4 = i & 15;
            float4 kv = *(const float4*)(Kp + (size_t)(kt * 64 + row) * DD + d4 * 4);
            __nv_bfloat16 h0 = __float2bfloat16(kv.x);
            __nv_bfloat16 h1 = __float2bfloat16(kv.y);
            __nv_bfloat16 h2 = __float2bfloat16(kv.z);
            __nv_bfloat16 h3 = __float2bfloat16(kv.w);
            sm[OKH + row * PW + d4 * 2]     = pkb2(h0, h1);
            sm[OKH + row * PW + d4 * 2 + 1] = pkb2(h2, h3);
            sm[OKL + row * PW + d4 * 2]     = pkbf(kv.x - __bfloat162float(h0),
                                                   kv.y - __bfloat162float(h1));
            sm[OKL + row * PW + d4 * 2 + 1] = pkbf(kv.z - __bfloat162float(h2),
                                                   kv.w - __bfloat162float(h3));
            float4 vv = *(const float4*)(Vp + (size_t)(kt * 64 + row) * DD + d4 * 4);
            sm[OVH + row * PW + d4 * 2]     = pkh(vv.x, vv.y);
            sm[OVH + row * PW + d4 * 2 + 1] = pkh(vv.z, vv.w);
        }
        __syncthreads();

        // ---- S = Q K^T (split bf16, 3 MMAs per tile) ----
        float sacc[8][4];
#pragma unroll
        for (int t = 0; t < 8; t++)
#pragma unroll
            for (int q = 0; q < 4; q++) sacc[t][q] = 0.0f;

#pragma unroll
        for (int j = 0; j < 4; j++) {
            unsigned ah[4], al[4];
            ah[0] = sm[OQH + r0 * PW + j * 8 + th];
            ah[1] = sm[OQH + (r0 + 8) * PW + j * 8 + th];
            ah[2] = sm[OQH + r0 * PW + j * 8 + th + 4];
            ah[3] = sm[OQH + (r0 + 8) * PW + j * 8 + th + 4];
            al[0] = sm[OQL + r0 * PW + j * 8 + th];
            al[1] = sm[OQL + (r0 + 8) * PW + j * 8 + th];
            al[2] = sm[OQL + r0 * PW + j * 8 + th + 4];
            al[3] = sm[OQL + (r0 + 8) * PW + j * 8 + th + 4];
#pragma unroll
            for (int t = 0; t < 8; t++) {
                unsigned bh2[2] = { sm[OKH + (t * 8 + g) * PW + j * 8 + th],
                                    sm[OKH + (t * 8 + g) * PW + j * 8 + th + 4] };
                unsigned bl2[2] = { sm[OKL + (t * 8 + g) * PW + j * 8 + th],
                                    sm[OKL + (t * 8 + g) * PW + j * 8 + th + 4] };
                mma_bf16(sacc[t], ah, bh2);
                mma_bf16(sacc[t], ah, bl2);
                mma_bf16(sacc[t], al, bh2);
            }
        }

        // ---- scale, mask, online softmax (quad-local reductions) ----
        const int kbase = kt * 64 + 2 * th;
        float mx0 = -INFINITY, mx1 = -INFINITY;
#pragma unroll
        for (int t = 0; t < 8; t++) {
            int kc = kbase + t * 8;
            float v0 = sacc[t][0] * 0.25f; if (kc     <= qrow0) v0 = NEGV;
            float v1 = sacc[t][1] * 0.25f; if (kc + 1 <= qrow0) v1 = NEGV;
            float v2 = sacc[t][2] * 0.25f; if (kc     <= qrow1) v2 = NEGV;
            float v3 = sacc[t][3] * 0.25f; if (kc + 1 <= qrow1) v3 = NEGV;
            sacc[t][0] = v0; sacc[t][1] = v1; sacc[t][2] = v2; sacc[t][3] = v3;
            mx0 = fmaxf(mx0, fmaxf(v0, v1));
            mx1 = fmaxf(mx1, fmaxf(v2, v3));
        }
        mx0 = fmaxf(mx0, __shfl_xor_sync(0xffffffffu, mx0, 1));
        mx0 = fmaxf(mx0, __shfl_xor_sync(0xffffffffu, mx0, 2));
        mx1 = fmaxf(mx1, __shfl_xor_sync(0xffffffffu, mx1, 1));
        mx1 = fmaxf(mx1, __shfl_xor_sync(0xffffffffu, mx1, 2));

        float mn0 = fmaxf(m2[0], mx0), mn1 = fmaxf(m2[1], mx1);
        float f0 = __expf(m2[0] - mn0), f1 = __expf(m2[1] - mn1);
        float s0 = 0.0f, s1 = 0.0f;
#pragma unroll
        for (int t = 0; t < 8; t++) {
            sacc[t][0] = __expf(sacc[t][0] - mn0);
            sacc[t][1] = __expf(sacc[t][1] - mn0);
            sacc[t][2] = __expf(sacc[t][2] - mn1);
            sacc[t][3] = __expf(sacc[t][3] - mn1);
            s0 += sacc[t][0] + sacc[t][1];
            s1 += sacc[t][2] + sacc[t][3];
        }
        s0 += __shfl_xor_sync(0xffffffffu, s0, 1);
        s0 += __shfl_xor_sync(0xffffffffu, s0, 2);
        s1 += __shfl_xor_sync(0xffffffffu, s1, 1);
        s1 += __shfl_xor_sync(0xffffffffu, s1, 2);
        l2[0] = l2[0] * f0 + s0;  m2[0] = mn0;
        l2[1] = l2[1] * f1 + s1;  m2[1] = mn1;
#pragma unroll
        for (int t = 0; t < 8; t++) {
            oacc[t][0] *= f0; oacc[t][1] *= f0;
            oacc[t][2] *= f1; oacc[t][3] *= f1;
        }

        // ---- O += P V (fp16).  P fragments repacked from sacc registers. ----
#pragma unroll
        for (int j = 0; j < 4; j++) {
            unsigned pa[4];
            pa[0] = pkh(sacc[2 * j][0],     sacc[2 * j][1]);
            pa[1] = pkh(sacc[2 * j][2],     sacc[2 * j][3]);
            pa[2] = pkh(sacc[2 * j + 1][0], sacc[2 * j + 1][1]);
            pa[3] = pkh(sacc[2 * j + 1][2], sacc[2 * j + 1][3]);
            unsigned vaddr = smem_u32 +
                (OVH + (j * 16 + (lane & 15)) * PW) * 4;
#pragma unroll
            for (int t = 0; t < 8; t++) {
                unsigned vb[2];
                asm volatile(
                    "ldmatrix.sync.aligned.m8n8.x2.trans.shared.b16 {%0,%1}, [%2];"
                    : "=r"(vb[0]), "=r"(vb[1]) : "r"(vaddr + t * 16));
                mma_f16(oacc[t], pa, vb);
            }
        }
    }

    // ---- epilogue ----
    float il0 = 1.0f / l2[0], il1 = 1.0f / l2[1];
#pragma unroll
    for (int t = 0; t < 8; t++) {
        int col = h * 64 + t * 8 + 2 * th;
        float2 o0, o1;
        o0.x = oacc[t][0] * il0;  o0.y = oacc[t][1] * il0;
        o1.x = oacc[t][2] * il1;  o1.y = oacc[t][3] * il1;
        *(float2*)&out[((size_t)b * SS + qrow0) * DD + col] = o0;
        *(float2*)&out[((size_t)b * SS + qrow1) * DD + col] = o1;
    }
}

// ---------------------------------------------------------------------------
// Fixup: row q = S-1 -> uniform softmax over ALL S keys -> mean_k V.
// ---------------------------------------------------------------------------
__global__ __launch_bounds__(256) void fix_last_row(float* __restrict__ out)
{
    __shared__ float red[256];
    const int bh = blockIdx.x;
    const int b = bh >> 4, h = bh & 15;
    const int d = threadIdx.x & 63;
    const int part = threadIdx.x >> 6;

    const float* vp = (const float*)g_Vv + (size_t)b * SS * DD + (size_t)h * DHD + d;
    float s = 0.0f;
    const int k_beg = part * (SS / 4), k_end = k_beg + SS / 4;
    for (int k = k_beg; k < k_end; k++)
        s += vp[(size_t)k * DD];
    red[threadIdx.x] = s;
    __syncthreads();
    if (part == 0) {
        float t = red[d] + red[64 + d] + red[128 + d] + red[192 + d];
        out[((size_t)b * SS + (SS - 1)) * DD + h * DHD + d] = t * (1.0f / SS);
    }
}

// ---------------------------------------------------------------------------
extern "C" void kernel_launch(void* const* d_in, const int* in_sizes, int n_in,
                              void* d_out, int out_size)
{
    const float* x  = (const float*)d_in[0];
    const float* Wq = (const float*)d_in[1];
    const float* bq = (const float*)d_in[2];
    const float* Wk = (const float*)d_in[3];
    const float* bk = (const float*)d_in[4];
    const float* Wv = (const float*)d_in[5];
    const float* bv = (const float*)d_in[6];
    float* out = (float*)d_out;

    static bool attr_done = false;
    if (!attr_done) {
        cudaFuncSetAttribute(attn_tc,
                             cudaFuncAttributeMaxDynamicSharedMemorySize,
                             ATTN2_BYTES);
        attr_done = true;
    }

    // Split inputs into bf16 hi/lo (destinations resolved device-side)
    split_f32<<<MM * DD / 1024, 256>>>(x, 0, 0);
    split_f32<<<DD * DD / 1024, 256>>>(Wq, 1, 0);
    split_f32<<<DD * DD / 1024, 256>>>(Wk, 1, (size_t)DD * DD);
    split_f32<<<DD * DD / 1024, 256>>>(Wv, 1, (size_t)2 * DD * DD);

    // Tensor-core QKV projections
    dim3 gt(DD / TBN, MM / TBM, 3);   // (8, 32, 3)
    qkv_gemm_tc<<<gt, 256>>>(bq, bk, bv);

    // Tensor-core flash attention
    attn_tc<<<dim3(SS / 128, BB * HH), 256, ATTN2_BYTES>>>(out);

    fix_last_row<<<BB * HH, 256>>>(out);
}

// round 13
// speedup vs baseline: 2.5541x; 1.0570x over previous
#include <cuda_runtime.h>
#include <cuda_bf16.h>
#include <cuda_fp16.h>
#include <math.h>
#include <cstdint>
#include <cstddef>

#define BB   2
#define SS   2048
#define DD   1024
#define HH   16
#define DHD  64
#define MM   (BB * SS)   // 4096

// Projection outputs, stored directly in attention-ready formats:
// Q (pre-scaled by 1/4) and K as split bf16 hi/lo; V as fp16.
__device__ __nv_bfloat16 g_Qhi[(size_t)MM * DD];
__device__ __nv_bfloat16 g_Qlo[(size_t)MM * DD];
__device__ __nv_bfloat16 g_Khi[(size_t)MM * DD];
__device__ __nv_bfloat16 g_Klo[(size_t)MM * DD];
__device__ __half        g_Vh [(size_t)MM * DD];

// bf16 hi/lo split operands for the projection GEMMs
__device__ __nv_bfloat16 g_Xhi[(size_t)MM * DD];
__device__ __nv_bfloat16 g_Xlo[(size_t)MM * DD];
__device__ __nv_bfloat16 g_Whi[(size_t)3 * DD * DD];
__device__ __nv_bfloat16 g_Wlo[(size_t)3 * DD * DD];

// ---------------------------------------------------------------------------
// helpers
// ---------------------------------------------------------------------------
__device__ __forceinline__ unsigned pkb2(__nv_bfloat16 a, __nv_bfloat16 b) {
    __nv_bfloat162 t; t.x = a; t.y = b; return *(unsigned*)&t;
}
__device__ __forceinline__ unsigned pkbf(float a, float b) {
    __nv_bfloat162 t = __floats2bfloat162_rn(a, b); return *(unsigned*)&t;
}
__device__ __forceinline__ unsigned pkh(float a, float b) {
    __half2 t = __floats2half2_rn(a, b); return *(unsigned*)&t;
}

// ---------------------------------------------------------------------------
// Split f32 -> bf16 hi + bf16 lo.  Destinations resolved IN DEVICE CODE.
// ---------------------------------------------------------------------------
__global__ __launch_bounds__(256) void split_f32(
    const float* __restrict__ src, int buf, size_t off)
{
    __nv_bfloat16* hi = (buf == 0) ? g_Xhi : (g_Whi + off);
    __nv_bfloat16* lo = (buf == 0) ? g_Xlo : (g_Wlo + off);

    int i = (blockIdx.x * 256 + threadIdx.x) * 4;
    float4 v = *(const float4*)(src + i);
    __nv_bfloat16 h0 = __float2bfloat16(v.x);
    __nv_bfloat16 h1 = __float2bfloat16(v.y);
    __nv_bfloat16 h2 = __float2bfloat16(v.z);
    __nv_bfloat16 h3 = __float2bfloat16(v.w);
    *(unsigned*)(hi + i)     = pkb2(h0, h1);
    *(unsigned*)(hi + i + 2) = pkb2(h2, h3);
    *(unsigned*)(lo + i)     = pkbf(v.x - __bfloat162float(h0),
                                    v.y - __bfloat162float(h1));
    *(unsigned*)(lo + i + 2) = pkbf(v.z - __bfloat162float(h2),
                                    v.w - __bfloat162float(h3));
}

// ---------------------------------------------------------------------------
// mma wrappers
// ---------------------------------------------------------------------------
__device__ __forceinline__ void mma_bf16(float (&c)[4], const unsigned (&a)[4],
                                         const unsigned (&b)[2])
{
    asm volatile(
        "mma.sync.aligned.m16n8k16.row.col.f32.bf16.bf16.f32 "
        "{%0,%1,%2,%3}, {%4,%5,%6,%7}, {%8,%9}, {%0,%1,%2,%3};"
        : "+f"(c[0]), "+f"(c[1]), "+f"(c[2]), "+f"(c[3])
        : "r"(a[0]), "r"(a[1]), "r"(a[2]), "r"(a[3]), "r"(b[0]), "r"(b[1]));
}
__device__ __forceinline__ void mma_f16(float (&c)[4], const unsigned (&a)[4],
                                        const unsigned (&b)[2])
{
    asm volatile(
        "mma.sync.aligned.m16n8k16.row.col.f32.f16.f16.f32 "
        "{%0,%1,%2,%3}, {%4,%5,%6,%7}, {%8,%9}, {%0,%1,%2,%3};"
        : "+f"(c[0]), "+f"(c[1]), "+f"(c[2]), "+f"(c[3])
        : "r"(a[0]), "r"(a[1]), "r"(a[2]), "r"(a[3]), "r"(b[0]), "r"(b[1]));
}

// ---------------------------------------------------------------------------
// QKV GEMM (legacy mma.sync bf16 split, cp.async double-buffered).
// C[m,n] = sum_k X[m,k]*W[n,k] + b[n].  Block tile 128x128, BK=32 bf16.
// 8 warps (4M x 2N), warp tile 32x64.  smem pitch 20 words (conflict-free).
// Epilogue: z=0 -> Q*(1/4) split bf16; z=1 -> K split bf16; z=2 -> V fp16.
// ---------------------------------------------------------------------------
#define QSPW 20
#define QTILE_W (128 * QSPW)          // 2560 words per tile
#define QSTAGE_W (4 * QTILE_W)        // 10240 words per stage
#define QSMEM_B (2 * QSTAGE_W * 4)    // 81920 bytes

__global__ __launch_bounds__(256) void qkv_tc(
    const float* __restrict__ bq,
    const float* __restrict__ bk,
    const float* __restrict__ bv)
{
    extern __shared__ unsigned qsm[];

    const int z = blockIdx.z;
    const float* bias = (z == 0) ? bq : (z == 1) ? bk : bv;
    const __nv_bfloat16* Whi = g_Whi + (size_t)z * DD * DD;
    const __nv_bfloat16* Wlo = g_Wlo + (size_t)z * DD * DD;

    const int tid = threadIdx.x;
    const int lane = tid & 31, wid = tid >> 5;
    const int wm = wid & 3, wn = wid >> 2;
    const int g = lane >> 2, th = lane & 3;
    const int m0 = blockIdx.y * 128;
    const int n0 = blockIdx.x * 128;
    const unsigned sm32 = (unsigned)__cvta_generic_to_shared(qsm);

    float acc[2][8][4];
#pragma unroll
    for (int ms = 0; ms < 2; ms++)
#pragma unroll
        for (int ns = 0; ns < 8; ns++)
#pragma unroll
            for (int q = 0; q < 4; q++) acc[ms][ns][q] = 0.0f;

    auto load_stage = [&](int kt, int s) {
        const int k0 = kt * 32;
#pragma unroll
        for (int p = 0; p < 8; p++) {
            int i = tid + p * 256;
            int t = i >> 9, r = (i >> 2) & 127, c = i & 3;
            const __nv_bfloat16* src;
            if (t == 0)      src = g_Xhi + (size_t)(m0 + r) * DD;
            else if (t == 1) src = g_Xlo + (size_t)(m0 + r) * DD;
            else if (t == 2) src = Whi  + (size_t)(n0 + r) * DD;
            else             src = Wlo  + (size_t)(n0 + r) * DD;
            unsigned da = sm32 +
                (unsigned)(s * QSTAGE_W + t * QTILE_W + r * QSPW + c * 4) * 4u;
            asm volatile("cp.async.cg.shared.global [%0], [%1], 16;"
                         :: "r"(da), "l"(src + k0 + c * 8));
        }
        asm volatile("cp.async.commit_group;" ::: "memory");
    };

    load_stage(0, 0);
    for (int kt = 0; kt < 32; kt++) {
        if (kt < 31) {
            load_stage(kt + 1, (kt + 1) & 1);
            asm volatile("cp.async.wait_group 1;" ::: "memory");
        } else {
            asm volatile("cp.async.wait_group 0;" ::: "memory");
        }
        __syncthreads();

        const unsigned* sAhi = qsm + (kt & 1) * QSTAGE_W;
        const unsigned* sAlo = sAhi + QTILE_W;
        const unsigned* sBhi = sAlo + QTILE_W;
        const unsigned* sBlo = sBhi + QTILE_W;

#pragma unroll
        for (int ks = 0; ks < 2; ks++) {
            const int c = ks * 8 + th;
            unsigned ah[2][4], al[2][4];
#pragma unroll
            for (int ms = 0; ms < 2; ms++) {
                int r0 = wm * 32 + ms * 16 + g;
                ah[ms][0] = sAhi[r0 * QSPW + c];
                ah[ms][1] = sAhi[(r0 + 8) * QSPW + c];
                ah[ms][2] = sAhi[r0 * QSPW + c + 4];
                ah[ms][3] = sAhi[(r0 + 8) * QSPW + c + 4];
                al[ms][0] = sAlo[r0 * QSPW + c];
                al[ms][1] = sAlo[(r0 + 8) * QSPW + c];
                al[ms][2] = sAlo[r0 * QSPW + c + 4];
                al[ms][3] = sAlo[(r0 + 8) * QSPW + c + 4];
            }
#pragma unroll
            for (int ns = 0; ns < 8; ns++) {
                int n = wn * 64 + ns * 8 + g;
                unsigned bh2[2] = { sBhi[n * QSPW + c], sBhi[n * QSPW + c + 4] };
                unsigned bl2[2] = { sBlo[n * QSPW + c], sBlo[n * QSPW + c + 4] };
#pragma unroll
                for (int ms = 0; ms < 2; ms++) {
                    mma_bf16(acc[ms][ns], ah[ms], bh2);
                    mma_bf16(acc[ms][ns], ah[ms], bl2);
                    mma_bf16(acc[ms][ns], al[ms], bh2);
                }
            }
        }
        __syncthreads();
    }

    // Epilogue: c0,c1 -> (m, n..n+1); c2,c3 -> (m+8, n..n+1)
    const float qscale = (z == 0) ? 0.25f : 1.0f;
#pragma unroll
    for (int ms = 0; ms < 2; ms++) {
        int m = m0 + wm * 32 + ms * 16 + g;
#pragma unroll
        for (int ns = 0; ns < 8; ns++) {
            int n = n0 + wn * 64 + ns * 8 + th * 2;
            float2 bb = *(const float2*)&bias[n];
            float o0x = (acc[ms][ns][0] + bb.x) * qscale;
            float o0y = (acc[ms][ns][1] + bb.y) * qscale;
            float o1x = (acc[ms][ns][2] + bb.x) * qscale;
            float o1y = (acc[ms][ns][3] + bb.y) * qscale;
            size_t i0 = (size_t)m * DD + n;
            size_t i1 = (size_t)(m + 8) * DD + n;
            if (z == 2) {
                *(unsigned*)&g_Vh[i0] = pkh(o0x, o0y);
                *(unsigned*)&g_Vh[i1] = pkh(o1x, o1y);
            } else {
                __nv_bfloat16* Hi = (z == 0) ? g_Qhi : g_Khi;
                __nv_bfloat16* Lo = (z == 0) ? g_Qlo : g_Klo;
                __nv_bfloat16 h0x = __float2bfloat16(o0x);
                __nv_bfloat16 h0y = __float2bfloat16(o0y);
                __nv_bfloat16 h1x = __float2bfloat16(o1x);
                __nv_bfloat16 h1y = __float2bfloat16(o1y);
                *(unsigned*)&Hi[i0] = pkb2(h0x, h0y);
                *(unsigned*)&Hi[i1] = pkb2(h1x, h1y);
                *(unsigned*)&Lo[i0] = pkbf(o0x - __bfloat162float(h0x),
                                           o0y - __bfloat162float(h0y));
                *(unsigned*)&Lo[i1] = pkbf(o1x - __bfloat162float(h1x),
                                           o1y - __bfloat162float(h1y));
            }
        }
    }
}

// ---------------------------------------------------------------------------
// Tensor-core flash attention, ANTI-causal mask (keep k > q).
// Q pre-scaled by 1/4; Q/K arrive pre-split bf16, V arrives fp16:
// tile loads are pure uint4 copies (no conversion math).
// ---------------------------------------------------------------------------
#define PW 36
#define OQH 0
#define OQL (128 * PW)
#define OKH (2 * 128 * PW)
#define OKL (OKH + 64 * PW)
#define OVH (OKL + 64 * PW)
#define ATTN2_WORDS (OVH + 64 * PW)
#define ATTN2_BYTES (ATTN2_WORDS * 4)
#define NEGV (-1000000000.0f)

__global__ __launch_bounds__(256) void attn_tc(float* __restrict__ out)
{
    extern __shared__ unsigned sm[];
    const int tid = threadIdx.x;
    const int qt = blockIdx.x;
    const int bh = blockIdx.y;
    const int b = bh >> 4, h = bh & 15;
    const int lane = tid & 31, wm = tid >> 5;
    const int g = lane >> 2, th = lane & 3;

    const size_t base = (size_t)b * SS * DD + (size_t)h * DHD;
    const int q0 = qt * 128;

    // Q tile (128 x 64), hi + lo: 2048 uint4 copies
    for (int i = tid; i < 2048; i += 256) {
        int arr = i >> 10, r = (i >> 3) & 127, c = i & 7;
        const __nv_bfloat16* src = (arr ? g_Qlo : g_Qhi) + base
                                 + (size_t)(q0 + r) * DD + c * 8;
        *(uint4*)&sm[(arr ? OQL : OQH) + r * PW + c * 4] = *(const uint4*)src;
    }

    float m2[2] = { -INFINITY, -INFINITY };
    float l2[2] = { 0.0f, 0.0f };
    float oacc[8][4];
#pragma unroll
    for (int t = 0; t < 8; t++)
#pragma unroll
        for (int q = 0; q < 4; q++) oacc[t][q] = 0.0f;

    const unsigned smem_u32 = (unsigned)__cvta_generic_to_shared(sm);
    const int r0 = wm * 16 + g;
    const int qrow0 = q0 + r0, qrow1 = qrow0 + 8;

    for (int kt = qt * 2; kt < SS / 64; kt++) {
        __syncthreads();
        // K hi/lo + V tiles (64 x 64): 1536 uint4 copies
        for (int i = tid; i < 1536; i += 256) {
            int t = i >> 9, r = (i >> 3) & 63, c = i & 7;
            size_t goff = base + (size_t)(kt * 64 + r) * DD + c * 8;
            const uint4* src;
            int dofs;
            if (t == 0)      { src = (const uint4*)(g_Khi + goff); dofs = OKH; }
            else if (t == 1) { src = (const uint4*)(g_Klo + goff); dofs = OKL; }
            else             { src = (const uint4*)(g_Vh  + goff); dofs = OVH; }
            *(uint4*)&sm[dofs + r * PW + c * 4] = *src;
        }
        __syncthreads();

        // ---- S = Q K^T (split bf16, 3 MMAs) ----
        float sacc[8][4];
#pragma unroll
        for (int t = 0; t < 8; t++)
#pragma unroll
            for (int q = 0; q < 4; q++) sacc[t][q] = 0.0f;

#pragma unroll
        for (int j = 0; j < 4; j++) {
            unsigned ah[4], al[4];
            ah[0] = sm[OQH + r0 * PW + j * 8 + th];
            ah[1] = sm[OQH + (r0 + 8) * PW + j * 8 + th];
            ah[2] = sm[OQH + r0 * PW + j * 8 + th + 4];
            ah[3] = sm[OQH + (r0 + 8) * PW + j * 8 + th + 4];
            al[0] = sm[OQL + r0 * PW + j * 8 + th];
            al[1] = sm[OQL + (r0 + 8) * PW + j * 8 + th];
            al[2] = sm[OQL + r0 * PW + j * 8 + th + 4];
            al[3] = sm[OQL + (r0 + 8) * PW + j * 8 + th + 4];
#pragma unroll
            for (int t = 0; t < 8; t++) {
                unsigned bh2[2] = { sm[OKH + (t * 8 + g) * PW + j * 8 + th],
                                    sm[OKH + (t * 8 + g) * PW + j * 8 + th + 4] };
                unsigned bl2[2] = { sm[OKL + (t * 8 + g) * PW + j * 8 + th],
                                    sm[OKL + (t * 8 + g) * PW + j * 8 + th + 4] };
                mma_bf16(sacc[t], ah, bh2);
                mma_bf16(sacc[t], ah, bl2);
                mma_bf16(sacc[t], al, bh2);
            }
        }

        // ---- mask (scores already scaled), online softmax ----
        const int kbase = kt * 64 + 2 * th;
        float mx0 = -INFINITY, mx1 = -INFINITY;
#pragma unroll
        for (int t = 0; t < 8; t++) {
            int kc = kbase + t * 8;
            float v0 = sacc[t][0]; if (kc     <= qrow0) v0 = NEGV;
            float v1 = sacc[t][1]; if (kc + 1 <= qrow0) v1 = NEGV;
            float v2 = sacc[t][2]; if (kc     <= qrow1) v2 = NEGV;
            float v3 = sacc[t][3]; if (kc + 1 <= qrow1) v3 = NEGV;
            sacc[t][0] = v0; sacc[t][1] = v1; sacc[t][2] = v2; sacc[t][3] = v3;
            mx0 = fmaxf(mx0, fmaxf(v0, v1));
            mx1 = fmaxf(mx1, fmaxf(v2, v3));
        }
        mx0 = fmaxf(mx0, __shfl_xor_sync(0xffffffffu, mx0, 1));
        mx0 = fmaxf(mx0, __shfl_xor_sync(0xffffffffu, mx0, 2));
        mx1 = fmaxf(mx1, __shfl_xor_sync(0xffffffffu, mx1, 1));
        mx1 = fmaxf(mx1, __shfl_xor_sync(0xffffffffu, mx1, 2));

        float mn0 = fmaxf(m2[0], mx0), mn1 = fmaxf(m2[1], mx1);
        float f0 = __expf(m2[0] - mn0), f1 = __expf(m2[1] - mn1);
        float s0 = 0.0f, s1 = 0.0f;
#pragma unroll
        for (int t = 0; t < 8; t++) {
            sacc[t][0] = __expf(sacc[t][0] - mn0);
            sacc[t][1] = __expf(sacc[t][1] - mn0);
            sacc[t][2] = __expf(sacc[t][2] - mn1);
            sacc[t][3] = __expf(sacc[t][3] - mn1);
            s0 += sacc[t][0] + sacc[t][1];
            s1 += sacc[t][2] + sacc[t][3];
        }
        s0 += __shfl_xor_sync(0xffffffffu, s0, 1);
        s0 += __shfl_xor_sync(0xffffffffu, s0, 2);
        s1 += __shfl_xor_sync(0xffffffffu, s1, 1);
        s1 += __shfl_xor_sync(0xffffffffu, s1, 2);
        l2[0] = l2[0] * f0 + s0;  m2[0] = mn0;
        l2[1] = l2[1] * f1 + s1;  m2[1] = mn1;
#pragma unroll
        for (int t = 0; t < 8; t++) {
            oacc[t][0] *= f0; oacc[t][1] *= f0;
            oacc[t][2] *= f1; oacc[t][3] *= f1;
        }

        // ---- O += P V (fp16), P fragments straight from registers ----
#pragma unroll
        for (int j = 0; j < 4; j++) {
            unsigned pa[4];
            pa[0] = pkh(sacc[2 * j][0],     sacc[2 * j][1]);
            pa[1] = pkh(sacc[2 * j][2],     sacc[2 * j][3]);
            pa[2] = pkh(sacc[2 * j + 1][0], sacc[2 * j + 1][1]);
            pa[3] = pkh(sacc[2 * j + 1][2], sacc[2 * j + 1][3]);
            unsigned vaddr = smem_u32 +
                (OVH + (j * 16 + (lane & 15)) * PW) * 4;
#pragma unroll
            for (int t = 0; t < 8; t++) {
                unsigned vb[2];
                asm volatile(
                    "ldmatrix.sync.aligned.m8n8.x2.trans.shared.b16 {%0,%1}, [%2];"
                    : "=r"(vb[0]), "=r"(vb[1]) : "r"(vaddr + t * 16));
                mma_f16(oacc[t], pa, vb);
            }
        }
    }

    float il0 = 1.0f / l2[0], il1 = 1.0f / l2[1];
#pragma unroll
    for (int t = 0; t < 8; t++) {
        int col = h * 64 + t * 8 + 2 * th;
        float2 o0, o1;
        o0.x = oacc[t][0] * il0;  o0.y = oacc[t][1] * il0;
        o1.x = oacc[t][2] * il1;  o1.y = oacc[t][3] * il1;
        *(float2*)&out[((size_t)b * SS + qrow0) * DD + col] = o0;
        *(float2*)&out[((size_t)b * SS + qrow1) * DD + col] = o1;
    }
}

// ---------------------------------------------------------------------------
// Fixup: row q = S-1 -> uniform softmax over ALL S keys -> mean_k V.
// ---------------------------------------------------------------------------
__global__ __launch_bounds__(256) void fix_last_row(float* __restrict__ out)
{
    __shared__ float red[256];
    const int bh = blockIdx.x;
    const int b = bh >> 4, h = bh & 15;
    const int d = threadIdx.x & 63;
    const int part = threadIdx.x >> 6;

    const __half* vp = g_Vh + (size_t)b * SS * DD + (size_t)h * DHD + d;
    float s = 0.0f;
    const int k_beg = part * (SS / 4), k_end = k_beg + SS / 4;
    for (int k = k_beg; k < k_end; k++)
        s += __half2float(vp[(size_t)k * DD]);
    red[threadIdx.x] = s;
    __syncthreads();
    if (part == 0) {
        float t = red[d] + red[64 + d] + red[128 + d] + red[192 + d];
        out[((size_t)b * SS + (SS - 1)) * DD + h * DHD + d] = t * (1.0f / SS);
    }
}

// ---------------------------------------------------------------------------
extern "C" void kernel_launch(void* const* d_in, const int* in_sizes, int n_in,
                              void* d_out, int out_size)
{
    const float* x  = (const float*)d_in[0];
    const float* Wq = (const float*)d_in[1];
    const float* bq = (const float*)d_in[2];
    const float* Wk = (const float*)d_in[3];
    const float* bk = (const float*)d_in[4];
    const float* Wv = (const float*)d_in[5];
    const float* bv = (const float*)d_in[6];
    float* out = (float*)d_out;

    static bool attr_done = false;
    if (!attr_done) {
        cudaFuncSetAttribute(attn_tc,
                             cudaFuncAttributeMaxDynamicSharedMemorySize,
                             ATTN2_BYTES);
        cudaFuncSetAttribute(qkv_tc,
                             cudaFuncAttributeMaxDynamicSharedMemorySize,
                             QSMEM_B);
        attr_done = true;
    }

    // Split inputs into bf16 hi/lo (destinations resolved device-side)
    split_f32<<<MM * DD / 1024, 256>>>(x, 0, 0);
    split_f32<<<DD * DD / 1024, 256>>>(Wq, 1, 0);
    split_f32<<<DD * DD / 1024, 256>>>(Wk, 1, (size_t)DD * DD);
    split_f32<<<DD * DD / 1024, 256>>>(Wv, 1, (size_t)2 * DD * DD);

    // QKV projections (legacy tensor-core, double-buffered cp.async)
    dim3 gt(DD / 128, MM / 128, 3);   // (8, 32, 3)
    qkv_tc<<<gt, 256, QSMEM_B>>>(bq, bk, bv);

    // Tensor-core flash attention
    attn_tc<<<dim3(SS / 128, BB * HH), 256, ATTN2_BYTES>>>(out);

    fix_last_row<<<BB * HH, 256>>>(out);
}

// round 14
// speedup vs baseline: 3.0692x; 1.2017x over previous
#include <cuda_runtime.h>
#include <cuda_bf16.h>
#include <cuda_fp16.h>
#include <math.h>
#include <cstdint>
#include <cstddef>

#define BB   2
#define SS   2048
#define DD   1024
#define HH   16
#define DHD  64
#define MM   (BB * SS)   // 4096

// Projection outputs, stored directly in attention-ready formats:
// Q (pre-scaled by 1/4) and K as split bf16 hi/lo; V as fp16.
__device__ __nv_bfloat16 g_Qhi[(size_t)MM * DD];
__device__ __nv_bfloat16 g_Qlo[(size_t)MM * DD];
__device__ __nv_bfloat16 g_Khi[(size_t)MM * DD];
__device__ __nv_bfloat16 g_Klo[(size_t)MM * DD];
__device__ __half        g_Vh [(size_t)MM * DD];

// bf16 hi/lo split operands for the projection GEMMs
__device__ __nv_bfloat16 g_Xhi[(size_t)MM * DD];
__device__ __nv_bfloat16 g_Xlo[(size_t)MM * DD];
__device__ __nv_bfloat16 g_Whi[(size_t)3 * DD * DD];
__device__ __nv_bfloat16 g_Wlo[(size_t)3 * DD * DD];

// ---------------------------------------------------------------------------
// helpers
// ---------------------------------------------------------------------------
__device__ __forceinline__ unsigned pkb2(__nv_bfloat16 a, __nv_bfloat16 b) {
    __nv_bfloat162 t; t.x = a; t.y = b; return *(unsigned*)&t;
}
__device__ __forceinline__ unsigned pkbf(float a, float b) {
    __nv_bfloat162 t = __floats2bfloat162_rn(a, b); return *(unsigned*)&t;
}
__device__ __forceinline__ unsigned pkh(float a, float b) {
    __half2 t = __floats2half2_rn(a, b); return *(unsigned*)&t;
}

#define LDSM4(r, a) asm volatile( \
    "ldmatrix.sync.aligned.m8n8.x4.shared.b16 {%0,%1,%2,%3}, [%4];" \
    : "=r"((r)[0]), "=r"((r)[1]), "=r"((r)[2]), "=r"((r)[3]) : "r"(a))

// ---------------------------------------------------------------------------
// Split f32 -> bf16 hi + bf16 lo.  Destinations resolved IN DEVICE CODE.
// ---------------------------------------------------------------------------
__global__ __launch_bounds__(256) void split_f32(
    const float* __restrict__ src, int buf, size_t off)
{
    __nv_bfloat16* hi = (buf == 0) ? g_Xhi : (g_Whi + off);
    __nv_bfloat16* lo = (buf == 0) ? g_Xlo : (g_Wlo + off);

    int i = (blockIdx.x * 256 + threadIdx.x) * 4;
    float4 v = *(const float4*)(src + i);
    __nv_bfloat16 h0 = __float2bfloat16(v.x);
    __nv_bfloat16 h1 = __float2bfloat16(v.y);
    __nv_bfloat16 h2 = __float2bfloat16(v.z);
    __nv_bfloat16 h3 = __float2bfloat16(v.w);
    *(unsigned*)(hi + i)     = pkb2(h0, h1);
    *(unsigned*)(hi + i + 2) = pkb2(h2, h3);
    *(unsigned*)(lo + i)     = pkbf(v.x - __bfloat162float(h0),
                                    v.y - __bfloat162float(h1));
    *(unsigned*)(lo + i + 2) = pkbf(v.z - __bfloat162float(h2),
                                    v.w - __bfloat162float(h3));
}

// ---------------------------------------------------------------------------
// mma wrappers
// ---------------------------------------------------------------------------
__device__ __forceinline__ void mma_bf16(float (&c)[4], const unsigned (&a)[4],
                                         unsigned b0, unsigned b1)
{
    asm volatile(
        "mma.sync.aligned.m16n8k16.row.col.f32.bf16.bf16.f32 "
        "{%0,%1,%2,%3}, {%4,%5,%6,%7}, {%8,%9}, {%0,%1,%2,%3};"
        : "+f"(c[0]), "+f"(c[1]), "+f"(c[2]), "+f"(c[3])
        : "r"(a[0]), "r"(a[1]), "r"(a[2]), "r"(a[3]), "r"(b0), "r"(b1));
}
__device__ __forceinline__ void mma_f16(float (&c)[4], const unsigned (&a)[4],
                                        unsigned b0, unsigned b1)
{
    asm volatile(
        "mma.sync.aligned.m16n8k16.row.col.f32.f16.f16.f32 "
        "{%0,%1,%2,%3}, {%4,%5,%6,%7}, {%8,%9}, {%0,%1,%2,%3};"
        : "+f"(c[0]), "+f"(c[1]), "+f"(c[2]), "+f"(c[3])
        : "r"(a[0]), "r"(a[1]), "r"(a[2]), "r"(a[3]), "r"(b0), "r"(b1));
}

// ---------------------------------------------------------------------------
// QKV GEMM (mma.sync bf16 split, cp.async double-buffered, ldmatrix frags).
// C[m,n] = sum_k X[m,k]*W[n,k] + b[n].  Block tile 128x128, BK=32 bf16.
// 8 warps (4M x 2N), warp tile 32x64.  smem pitch 20 words (conflict-free).
// Epilogue: z=0 -> Q*(1/4) split bf16; z=1 -> K split bf16; z=2 -> V fp16.
// ---------------------------------------------------------------------------
#define QSPW 20
#define QTILE_W (128 * QSPW)          // 2560 words per tile
#define QSTAGE_W (4 * QTILE_W)        // 10240 words per stage
#define QSMEM_B (2 * QSTAGE_W * 4)    // 81920 bytes

__global__ __launch_bounds__(256) void qkv_tc(
    const float* __restrict__ bq,
    const float* __restrict__ bk,
    const float* __restrict__ bv)
{
    extern __shared__ unsigned qsm[];

    const int z = blockIdx.z;
    const float* bias = (z == 0) ? bq : (z == 1) ? bk : bv;
    const __nv_bfloat16* Whi = g_Whi + (size_t)z * DD * DD;
    const __nv_bfloat16* Wlo = g_Wlo + (size_t)z * DD * DD;

    const int tid = threadIdx.x;
    const int lane = tid & 31, wid = tid >> 5;
    const int wm = wid & 3, wn = wid >> 2;
    const int g = lane >> 2, th = lane & 3;
    const int m0 = blockIdx.y * 128;
    const int n0 = blockIdx.x * 128;
    const unsigned sm32 = (unsigned)__cvta_generic_to_shared(qsm);

    // ldmatrix lane->element maps (A-style for m16 frags, B-style for n8 pairs)
    const int lr8 = (lane & 7) + ((lane >> 3) & 1) * 8;   // A row offset
    const int lcA = (lane >> 4) * 4;                      // A col offset (words)
    const int lrB = ((lane >> 4) << 3) + (lane & 7);      // B row offset
    const int lcB = ((lane >> 3) & 1) * 4;                // B col offset (words)

    float acc[2][8][4];
#pragma unroll
    for (int ms = 0; ms < 2; ms++)
#pragma unroll
        for (int ns = 0; ns < 8; ns++)
#pragma unroll
            for (int q = 0; q < 4; q++) acc[ms][ns][q] = 0.0f;

    auto load_stage = [&](int kt, int s) {
        const int k0 = kt * 32;
#pragma unroll
        for (int p = 0; p < 8; p++) {
            int i = tid + p * 256;
            int t = i >> 9, r = (i >> 2) & 127, c = i & 3;
            const __nv_bfloat16* src;
            if (t == 0)      src = g_Xhi + (size_t)(m0 + r) * DD;
            else if (t == 1) src = g_Xlo + (size_t)(m0 + r) * DD;
            else if (t == 2) src = Whi  + (size_t)(n0 + r) * DD;
            else             src = Wlo  + (size_t)(n0 + r) * DD;
            unsigned da = sm32 +
                (unsigned)(s * QSTAGE_W + t * QTILE_W + r * QSPW + c * 4) * 4u;
            asm volatile("cp.async.cg.shared.global [%0], [%1], 16;"
                         :: "r"(da), "l"(src + k0 + c * 8));
        }
        asm volatile("cp.async.commit_group;" ::: "memory");
    };

    load_stage(0, 0);
    for (int kt = 0; kt < 32; kt++) {
        if (kt < 31) {
            load_stage(kt + 1, (kt + 1) & 1);
            asm volatile("cp.async.wait_group 1;" ::: "memory");
        } else {
            asm volatile("cp.async.wait_group 0;" ::: "memory");
        }
        __syncthreads();

        const unsigned stg = sm32 + (unsigned)((kt & 1) * QSTAGE_W) * 4u;

#pragma unroll
        for (int ks = 0; ks < 2; ks++) {
            unsigned ah[2][4], al[2][4];
#pragma unroll
            for (int ms = 0; ms < 2; ms++) {
                unsigned aa = stg +
                    (unsigned)(((wm * 32 + ms * 16 + lr8) * QSPW) + ks * 8 + lcA) * 4u;
                LDSM4(ah[ms], aa);
                LDSM4(al[ms], aa + (unsigned)QTILE_W * 4u);
            }
#pragma unroll
            for (int p = 0; p < 4; p++) {
                unsigned bh4[4], bl4[4];
                unsigned ba = stg + (unsigned)(2 * QTILE_W +
                    (wn * 64 + p * 16 + lrB) * QSPW + ks * 8 + lcB) * 4u;
                LDSM4(bh4, ba);
                LDSM4(bl4, ba + (unsigned)QTILE_W * 4u);
#pragma unroll
                for (int ms = 0; ms < 2; ms++) {
                    mma_bf16(acc[ms][2 * p],     ah[ms], bh4[0], bh4[1]);
                    mma_bf16(acc[ms][2 * p],     ah[ms], bl4[0], bl4[1]);
                    mma_bf16(acc[ms][2 * p],     al[ms], bh4[0], bh4[1]);
                    mma_bf16(acc[ms][2 * p + 1], ah[ms], bh4[2], bh4[3]);
                    mma_bf16(acc[ms][2 * p + 1], ah[ms], bl4[2], bl4[3]);
                    mma_bf16(acc[ms][2 * p + 1], al[ms], bh4[2], bh4[3]);
                }
            }
        }
        __syncthreads();
    }

    // Epilogue: c0,c1 -> (m, n..n+1); c2,c3 -> (m+8, n..n+1)
    const float qscale = (z == 0) ? 0.25f : 1.0f;
#pragma unroll
    for (int ms = 0; ms < 2; ms++) {
        int m = m0 + wm * 32 + ms * 16 + g;
#pragma unroll
        for (int ns = 0; ns < 8; ns++) {
            int n = n0 + wn * 64 + ns * 8 + th * 2;
            float2 bb = *(const float2*)&bias[n];
            float o0x = (acc[ms][ns][0] + bb.x) * qscale;
            float o0y = (acc[ms][ns][1] + bb.y) * qscale;
            float o1x = (acc[ms][ns][2] + bb.x) * qscale;
            float o1y = (acc[ms][ns][3] + bb.y) * qscale;
            size_t i0 = (size_t)m * DD + n;
            size_t i1 = (size_t)(m + 8) * DD + n;
            if (z == 2) {
                *(unsigned*)&g_Vh[i0] = pkh(o0x, o0y);
                *(unsigned*)&g_Vh[i1] = pkh(o1x, o1y);
            } else {
                __nv_bfloat16* Hi = (z == 0) ? g_Qhi : g_Khi;
                __nv_bfloat16* Lo = (z == 0) ? g_Qlo : g_Klo;
                __nv_bfloat16 h0x = __float2bfloat16(o0x);
                __nv_bfloat16 h0y = __float2bfloat16(o0y);
                __nv_bfloat16 h1x = __float2bfloat16(o1x);
                __nv_bfloat16 h1y = __float2bfloat16(o1y);
                *(unsigned*)&Hi[i0] = pkb2(h0x, h0y);
                *(unsigned*)&Hi[i1] = pkb2(h1x, h1y);
                *(unsigned*)&Lo[i0] = pkbf(o0x - __bfloat162float(h0x),
                                           o0y - __bfloat162float(h0y));
                *(unsigned*)&Lo[i1] = pkbf(o1x - __bfloat162float(h1x),
                                           o1y - __bfloat162float(h1y));
            }
        }
    }
}

// ---------------------------------------------------------------------------
// Tensor-core flash attention, ANTI-causal mask (keep k > q).
// Q pre-scaled by 1/4; Q/K pre-split bf16, V fp16.  ldmatrix fragments.
// Grid: (bh, qt) so longest CTAs (qt=0) launch first.
// ---------------------------------------------------------------------------
#define PW 36
#define OQH 0
#define OQL (128 * PW)
#define OKH (2 * 128 * PW)
#define OKL (OKH + 64 * PW)
#define OVH (OKL + 64 * PW)
#define ATTN2_WORDS (OVH + 64 * PW)
#define ATTN2_BYTES (ATTN2_WORDS * 4)
#define NEGV (-1000000000.0f)

__global__ __launch_bounds__(256) void attn_tc(float* __restrict__ out)
{
    extern __shared__ unsigned sm[];
    const int tid = threadIdx.x;
    const int bh = blockIdx.x;
    const int qt = blockIdx.y;
    const int b = bh >> 4, h = bh & 15;
    const int lane = tid & 31, wm = tid >> 5;
    const int th = lane & 3;

    const size_t base = (size_t)b * SS * DD + (size_t)h * DHD;
    const int q0 = qt * 128;

    const int lr8 = (lane & 7) + ((lane >> 3) & 1) * 8;
    const int lcA = (lane >> 4) * 4;
    const int lrB = ((lane >> 4) << 3) + (lane & 7);
    const int lcB = ((lane >> 3) & 1) * 4;

    // Q tile (128 x 64), hi + lo: 2048 uint4 copies
    for (int i = tid; i < 2048; i += 256) {
        int arr = i >> 10, r = (i >> 3) & 127, c = i & 7;
        const __nv_bfloat16* src = (arr ? g_Qlo : g_Qhi) + base
                                 + (size_t)(q0 + r) * DD + c * 8;
        *(uint4*)&sm[(arr ? OQL : OQH) + r * PW + c * 4] = *(const uint4*)src;
    }

    float m2[2] = { -INFINITY, -INFINITY };
    float l2[2] = { 0.0f, 0.0f };
    float oacc[8][4];
#pragma unroll
    for (int t = 0; t < 8; t++)
#pragma unroll
        for (int q = 0; q < 4; q++) oacc[t][q] = 0.0f;

    const unsigned smem_u32 = (unsigned)__cvta_generic_to_shared(sm);
    const int r0 = wm * 16 + (lane >> 2);
    const int qrow0 = q0 + r0, qrow1 = qrow0 + 8;

    for (int kt = qt * 2; kt < SS / 64; kt++) {
        __syncthreads();
        // K hi/lo + V tiles (64 x 64): 1536 uint4 copies
        for (int i = tid; i < 1536; i += 256) {
            int t = i >> 9, r = (i >> 3) & 63, c = i & 7;
            size_t goff = base + (size_t)(kt * 64 + r) * DD + c * 8;
            const uint4* src;
            int dofs;
            if (t == 0)      { src = (const uint4*)(g_Khi + goff); dofs = OKH; }
            else if (t == 1) { src = (const uint4*)(g_Klo + goff); dofs = OKL; }
            else             { src = (const uint4*)(g_Vh  + goff); dofs = OVH; }
            *(uint4*)&sm[dofs + r * PW + c * 4] = *src;
        }
        __syncthreads();

        // ---- S = Q K^T (split bf16, 3 MMAs), ldmatrix fragments ----
        float sacc[8][4];
#pragma unroll
        for (int t = 0; t < 8; t++)
#pragma unroll
            for (int q = 0; q < 4; q++) sacc[t][q] = 0.0f;

#pragma unroll
        for (int j = 0; j < 4; j++) {
            unsigned ah[4], al[4];
            unsigned qa = smem_u32 +
                (unsigned)(OQH + (wm * 16 + lr8) * PW + j * 8 + lcA) * 4u;
            LDSM4(ah, qa);
            LDSM4(al, qa + (unsigned)(OQL - OQH) * 4u);
#pragma unroll
            for (int p = 0; p < 4; p++) {
                unsigned kh4[4], kl4[4];
                unsigned ka = smem_u32 +
                    (unsigned)(OKH + (p * 16 + lrB) * PW + j * 8 + lcB) * 4u;
                LDSM4(kh4, ka);
                LDSM4(kl4, ka + (unsigned)(OKL - OKH) * 4u);
                mma_bf16(sacc[2 * p],     ah, kh4[0], kh4[1]);
                mma_bf16(sacc[2 * p],     ah, kl4[0], kl4[1]);
                mma_bf16(sacc[2 * p],     al, kh4[0], kh4[1]);
                mma_bf16(sacc[2 * p + 1], ah, kh4[2], kh4[3]);
                mma_bf16(sacc[2 * p + 1], ah, kl4[2], kl4[3]);
                mma_bf16(sacc[2 * p + 1], al, kh4[2], kh4[3]);
            }
        }

        // ---- mask (scores already scaled), online softmax ----
        const int kbase = kt * 64 + 2 * th;
        float mx0 = -INFINITY, mx1 = -INFINITY;
#pragma unroll
        for (int t = 0; t < 8; t++) {
            int kc = kbase + t * 8;
            float v0 = sacc[t][0]; if (kc     <= qrow0) v0 = NEGV;
            float v1 = sacc[t][1]; if (kc + 1 <= qrow0) v1 = NEGV;
            float v2 = sacc[t][2]; if (kc     <= qrow1) v2 = NEGV;
            float v3 = sacc[t][3]; if (kc + 1 <= qrow1) v3 = NEGV;
            sacc[t][0] = v0; sacc[t][1] = v1; sacc[t][2] = v2; sacc[t][3] = v3;
            mx0 = fmaxf(mx0, fmaxf(v0, v1));
            mx1 = fmaxf(mx1, fmaxf(v2, v3));
        }
        mx0 = fmaxf(mx0, __shfl_xor_sync(0xffffffffu, mx0, 1));
        mx0 = fmaxf(mx0, __shfl_xor_sync(0xffffffffu, mx0, 2));
        mx1 = fmaxf(mx1, __shfl_xor_sync(0xffffffffu, mx1, 1));
        mx1 = fmaxf(mx1, __shfl_xor_sync(0xffffffffu, mx1, 2));

        float mn0 = fmaxf(m2[0], mx0), mn1 = fmaxf(m2[1], mx1);
        float f0 = __expf(m2[0] - mn0), f1 = __expf(m2[1] - mn1);
        float s0 = 0.0f, s1 = 0.0f;
#pragma unroll
        for (int t = 0; t < 8; t++) {
            sacc[t][0] = __expf(sacc[t][0] - mn0);
            sacc[t][1] = __expf(sacc[t][1] - mn0);
            sacc[t][2] = __expf(sacc[t][2] - mn1);
            sacc[t][3] = __expf(sacc[t][3] - mn1);
            s0 += sacc[t][0] + sacc[t][1];
            s1 += sacc[t][2] + sacc[t][3];
        }
        s0 += __shfl_xor_sync(0xffffffffu, s0, 1);
        s0 += __shfl_xor_sync(0xffffffffu, s0, 2);
        s1 += __shfl_xor_sync(0xffffffffu, s1, 1);
        s1 += __shfl_xor_sync(0xffffffffu, s1, 2);
        l2[0] = l2[0] * f0 + s0;  m2[0] = mn0;
        l2[1] = l2[1] * f1 + s1;  m2[1] = mn1;
#pragma unroll
        for (int t = 0; t < 8; t++) {
            oacc[t][0] *= f0; oacc[t][1] *= f0;
            oacc[t][2] *= f1; oacc[t][3] *= f1;
        }

        // ---- O += P V (fp16), P fragments straight from registers ----
#pragma unroll
        for (int j = 0; j < 4; j++) {
            unsigned pa[4];
            pa[0] = pkh(sacc[2 * j][0],     sacc[2 * j][1]);
            pa[1] = pkh(sacc[2 * j][2],     sacc[2 * j][3]);
            pa[2] = pkh(sacc[2 * j + 1][0], sacc[2 * j + 1][1]);
            pa[3] = pkh(sacc[2 * j + 1][2], sacc[2 * j + 1][3]);
            unsigned vaddr = smem_u32 +
                (unsigned)(OVH + (j * 16 + (lane & 15)) * PW) * 4u;
#pragma unroll
            for (int t = 0; t < 8; t++) {
                unsigned vb0, vb1;
                asm volatile(
                    "ldmatrix.sync.aligned.m8n8.x2.trans.shared.b16 {%0,%1}, [%2];"
                    : "=r"(vb0), "=r"(vb1) : "r"(vaddr + t * 16));
                mma_f16(oacc[t], pa, vb0, vb1);
            }
        }
    }

    float il0 = 1.0f / l2[0], il1 = 1.0f / l2[1];
#pragma unroll
    for (int t = 0; t < 8; t++) {
        int col = h * 64 + t * 8 + 2 * th;
        float2 o0, o1;
        o0.x = oacc[t][0] * il0;  o0.y = oacc[t][1] * il0;
        o1.x = oacc[t][2] * il1;  o1.y = oacc[t][3] * il1;
        *(float2*)&out[((size_t)b * SS + qrow0) * DD + col] = o0;
        *(float2*)&out[((size_t)b * SS + qrow1) * DD + col] = o1;
    }
}

// ---------------------------------------------------------------------------
// Fixup: row q = S-1 -> uniform softmax over ALL S keys -> mean_k V.
// ---------------------------------------------------------------------------
__global__ __launch_bounds__(256) void fix_last_row(float* __restrict__ out)
{
    __shared__ float red[256];
    const int bh = blockIdx.x;
    const int b = bh >> 4, h = bh & 15;
    const int d = threadIdx.x & 63;
    const int part = threadIdx.x >> 6;

    const __half* vp = g_Vh + (size_t)b * SS * DD + (size_t)h * DHD + d;
    float s = 0.0f;
    const int k_beg = part * (SS / 4), k_end = k_beg + SS / 4;
    for (int k = k_beg; k < k_end; k++)
        s += __half2float(vp[(size_t)k * DD]);
    red[threadIdx.x] = s;
    __syncthreads();
    if (part == 0) {
        float t = red[d] + red[64 + d] + red[128 + d] + red[192 + d];
        out[((size_t)b * SS + (SS - 1)) * DD + h * DHD + d] = t * (1.0f / SS);
    }
}

// ---------------------------------------------------------------------------
extern "C" void kernel_launch(void* const* d_in, const int* in_sizes, int n_in,
                              void* d_out, int out_size)
{
    const float* x  = (const float*)d_in[0];
    const float* Wq = (const float*)d_in[1];
    const float* bq = (const float*)d_in[2];
    const float* Wk = (const float*)d_in[3];
    const float* bk = (const float*)d_in[4];
    const float* Wv = (const float*)d_in[5];
    const float* bv = (const float*)d_in[6];
    float* out = (float*)d_out;

    static bool attr_done = false;
    if (!attr_done) {
        cudaFuncSetAttribute(attn_tc,
                             cudaFuncAttributeMaxDynamicSharedMemorySize,
                             ATTN2_BYTES);
        cudaFuncSetAttribute(qkv_tc,
                             cudaFuncAttributeMaxDynamicSharedMemorySize,
                             QSMEM_B);
        attr_done = true;
    }

    // Split inputs into bf16 hi/lo (destinations resolved device-side)
    split_f32<<<MM * DD / 1024, 256>>>(x, 0, 0);
    split_f32<<<DD * DD / 1024, 256>>>(Wq, 1, 0);
    split_f32<<<DD * DD / 1024, 256>>>(Wk, 1, (size_t)DD * DD);
    split_f32<<<DD * DD / 1024, 256>>>(Wv, 1, (size_t)2 * DD * DD);

    // QKV projections (tensor-core, cp.async double-buffered, ldmatrix)
    dim3 gt(DD / 128, MM / 128, 3);   // (8, 32, 3)
    qkv_tc<<<gt, 256, QSMEM_B>>>(bq, bk, bv);

    // Tensor-core flash attention (longest q-tiles scheduled first)
    attn_tc<<<dim3(BB * HH, SS / 128), 256, ATTN2_BYTES>>>(out);

    fix_last_row<<<BB * HH, 256>>>(out);
}